// round 7
// baseline (speedup 1.0000x reference)
#include <cuda_runtime.h>
#include <cstdint>

// ============================================================================
// Problem: B=8, N=1024, D=1024, H=16, dk=64
// out = (0.5*softmax(QK^T/8, key-masked) + 0.5*row_norm(adj)) @ V  -> @Wo + bo
// All heavy math on tensor cores via mma.sync tf32; tf32 roundings hoisted.
// R7: 512-thread GEMM (4 warps/SMSP), fused QKV launch, profiling-friendly order.
// ============================================================================

__device__ float g_Q[8u * 1024u * 1024u];
__device__ float g_K[8u * 1024u * 1024u];
__device__ float g_V[8u * 1024u * 1024u];
__device__ float g_X[8u * 1024u * 1024u];
__device__ float g_inv[8u * 1024u];
__device__ float g_tQin[8u * 1024u * 1024u];
__device__ float g_tKin[8u * 1024u * 1024u];
__device__ float g_tVin[8u * 1024u * 1024u];
__device__ float g_tAdj[8u * 1024u * 1024u];
__device__ float g_tW[4u * 1024u * 1024u];   // tf32(Wq|Wk|Wv|Wo)

// ---------------------------------------------------------------------------
__device__ __forceinline__ uint32_t smem_to_u32(const void* p) {
    uint32_t a;
    asm("{ .reg .u64 t; cvta.to.shared.u64 t, %1; cvt.u32.u64 %0, t; }" : "=r"(a) : "l"(p));
    return a;
}
__device__ __forceinline__ void cp_async16(uint32_t s, const void* g) {
    asm volatile("cp.async.cg.shared.global [%0], [%1], 16;" :: "r"(s), "l"(g));
}
#define CP_COMMIT() asm volatile("cp.async.commit_group;" ::: "memory")
#define CP_WAIT(n)  asm volatile("cp.async.wait_group %0;" :: "n"(n) : "memory")

__device__ __forceinline__ uint32_t f2tf32(float x) {
    uint32_t r;
    asm("cvt.rna.tf32.f32 %0, %1;" : "=r"(r) : "f"(x));
    return r;
}
__device__ __forceinline__ float tf32f(float x) {
    return __uint_as_float(f2tf32(x));
}
__device__ __forceinline__ void mma_tf32(float* c, const uint32_t* a, const uint32_t* b) {
    asm volatile(
        "mma.sync.aligned.m16n8k8.row.col.f32.tf32.tf32.f32 "
        "{%0,%1,%2,%3}, {%4,%5,%6,%7}, {%8,%9}, {%0,%1,%2,%3};"
        : "+f"(c[0]), "+f"(c[1]), "+f"(c[2]), "+f"(c[3])
        : "r"(a[0]), "r"(a[1]), "r"(a[2]), "r"(a[3]), "r"(b[0]), "r"(b[1]));
}

// ---------------------------------------------------------------------------
// fp32 -> tf32-valued fp32, elementwise
// ---------------------------------------------------------------------------
__global__ __launch_bounds__(256) void cvt_tf32(
    const float* __restrict__ in, float* __restrict__ out)
{
    int g = blockIdx.x * 256 + threadIdx.x;
    float4 v = ((const float4*)in)[g];
    ((float4*)out)[g] = make_float4(tf32f(v.x), tf32f(v.y), tf32f(v.z), tf32f(v.w));
}

// 4 weight matrices in one launch: grid (1024, 4)
__global__ __launch_bounds__(256) void cvt_w4(
    const float* __restrict__ w0, const float* __restrict__ w1,
    const float* __restrict__ w2, const float* __restrict__ w3,
    float* __restrict__ out)
{
    const float* src = (blockIdx.y == 0) ? w0 : (blockIdx.y == 1) ? w1
                     : (blockIdx.y == 2) ? w2 : w3;
    int g = blockIdx.x * 256 + threadIdx.x;
    float4 v = ((const float4*)src)[g];
    float4* o = (float4*)(out + (size_t)blockIdx.y * 1024u * 1024u);
    o[g] = make_float4(tf32f(v.x), tf32f(v.y), tf32f(v.z), tf32f(v.w));
}

// ---------------------------------------------------------------------------
// adjacency row-sum -> 1/(sum+eps); one warp per row, float4 loads
// ---------------------------------------------------------------------------
__global__ __launch_bounds__(256) void rowsum_inv(
    const float* __restrict__ adj, float* __restrict__ inv)
{
    const int row = blockIdx.x * 8 + (threadIdx.x >> 5);
    const int lane = threadIdx.x & 31;
    const float4* a = (const float4*)(adj + (size_t)row * 1024);
    float s = 0.f;
#pragma unroll
    for (int i = 0; i < 8; i++) {
        float4 v = a[lane + i * 32];
        s += (v.x + v.y) + (v.z + v.w);
    }
#pragma unroll
    for (int o = 16; o > 0; o >>= 1) s += __shfl_xor_sync(0xffffffffu, s, o);
    if (lane == 0) inv[row] = 1.0f / (s + 1e-6f);
}

// ---------------------------------------------------------------------------
// tf32 tensor-core GEMM, cvt-free mainloop. 512 threads, 16 warps (2m x 8n),
// block tile 128x256, warp tile 64x32, K-tile 32, 3-stage cp.async.
// nsel>1: blockIdx.z selects operand set (fused QKV); else blockIdx.z = batch.
// cmode 0: C = tf32(D + bias);  1: C = tf32(0.5*inv*D + Xin);  2: C = D + bias
// ---------------------------------------------------------------------------
#define PA 36
#define PB 264
#define A_STG (128 * PA)
#define B_STG (32 * PB)
#define STG_STRIDE (A_STG + B_STG)
#define NSTG 3
#define GEMM_SMEM (STG_STRIDE * NSTG * 4)   // 156672 bytes

struct GemmArgs {
    const float* A[3];
    const float* B[3];
    const float* bias[3];
    float* C[3];
    const float* inv;
    const float* Xin;
    size_t sA, sB, sC;
    int nsel;
    int cmode;
};

__global__ __launch_bounds__(512, 1) void gemm_tf32(GemmArgs args)
{
    extern __shared__ float sm[];
    const uint32_t base_u = smem_to_u32(sm);

    const int tid = threadIdx.x;
    const int wid = tid >> 5, lane = tid & 31;
    const int wm = wid >> 3, wn = wid & 7;      // 2 x 8 warps
    const int g = lane >> 2, t = lane & 3;

    const int sel = (args.nsel > 1) ? blockIdx.z : 0;
    const int z   = (args.nsel > 1) ? 0 : blockIdx.z;

    const float* Ab = args.A[sel] + (size_t)z * args.sA + (size_t)(blockIdx.y * 128) * 1024;
    const float* Bb = args.B[sel] + (size_t)z * args.sB + blockIdx.x * 256;

    // loaders: A 128x32 floats (1024 f4, 2/thread), B 32x256 (2048 f4, 4/thread)
    const int a_r = tid >> 3, a_c4 = (tid & 7) << 2;      // +i*64 rows
    const int b_r = tid >> 6, b_c4 = (tid & 63) << 2;     // +i*8 rows

    float c[4][4][4];
#pragma unroll
    for (int i = 0; i < 4; i++)
#pragma unroll
        for (int j = 0; j < 4; j++)
#pragma unroll
            for (int q = 0; q < 4; q++) c[i][j][q] = 0.f;

    auto load_stage = [&](int kt, int stg) {
        const uint32_t as_u = base_u + (uint32_t)(stg * STG_STRIDE) * 4;
        const uint32_t bs_u = as_u + (uint32_t)A_STG * 4;
#pragma unroll
        for (int i = 0; i < 2; i++) {
            int r = a_r + i * 64;
            cp_async16(as_u + (uint32_t)(r * PA + a_c4) * 4,
                       Ab + (size_t)r * 1024 + kt * 32 + a_c4);
        }
#pragma unroll
        for (int i = 0; i < 4; i++) {
            int r = b_r + i * 8;
            cp_async16(bs_u + (uint32_t)(r * PB + b_c4) * 4,
                       Bb + (size_t)(kt * 32 + r) * 1024 + b_c4);
        }
        CP_COMMIT();
    };

    load_stage(0, 0);
    load_stage(1, 1);

    int stg = 0;
    for (int kt = 0; kt < 32; kt++) {
        if (kt + 2 < 32) { load_stage(kt + 2, (kt + 2) % NSTG); CP_WAIT(2); }
        else if (kt + 1 < 32) { CP_WAIT(1); }
        else { CP_WAIT(0); }
        __syncthreads();

        const uint32_t* Ast = (const uint32_t*)(sm + stg * STG_STRIDE);
        const uint32_t* Bst = Ast + A_STG;
#pragma unroll
        for (int ks = 0; ks < 4; ks++) {
            const int k0 = ks * 8;
            uint32_t af[4][4];
#pragma unroll
            for (int i = 0; i < 4; i++) {
                const uint32_t* ar = Ast + (wm * 64 + i * 16 + g) * PA + k0 + t;
                af[i][0] = ar[0];
                af[i][1] = ar[8 * PA];
                af[i][2] = ar[4];
                af[i][3] = ar[8 * PA + 4];
            }
            uint32_t bf[4][2];
#pragma unroll
            for (int j = 0; j < 4; j++) {
                const uint32_t* br = Bst + (k0 + t) * PB + wn * 32 + j * 8 + g;
                bf[j][0] = br[0];
                bf[j][1] = br[4 * PB];
            }
#pragma unroll
            for (int i = 0; i < 4; i++)
#pragma unroll
                for (int j = 0; j < 4; j++)
                    mma_tf32(c[i][j], af[i], bf[j]);
        }
        __syncthreads();
        stg = (stg + 1) % NSTG;
    }

    // ---- epilogue ----
    const int colW = blockIdx.x * 256 + wn * 32;
    float* Cz = args.C[sel] + (size_t)z * args.sC;
    const float* Xz = args.Xin + (size_t)z * args.sC;
    const float* bias = args.bias[sel];
    const int cmode = args.cmode;

#pragma unroll
    for (int i = 0; i < 4; i++) {
        const int row0 = blockIdx.y * 128 + wm * 64 + i * 16 + g;
        const int row1 = row0 + 8;
        if (cmode == 0) {
#pragma unroll
            for (int j = 0; j < 4; j++) {
                const int col = colW + j * 8 + 2 * t;
                const float b0 = bias[col], b1 = bias[col + 1];
                *(float2*)(Cz + (size_t)row0 * 1024 + col) =
                    make_float2(tf32f(c[i][j][0] + b0), tf32f(c[i][j][1] + b1));
                *(float2*)(Cz + (size_t)row1 * 1024 + col) =
                    make_float2(tf32f(c[i][j][2] + b0), tf32f(c[i][j][3] + b1));
            }
        } else if (cmode == 1) {
            const float s0 = 0.5f * args.inv[z * 1024 + row0];
            const float s1 = 0.5f * args.inv[z * 1024 + row1];
#pragma unroll
            for (int j = 0; j < 4; j++) {
                const int col = colW + j * 8 + 2 * t;
                float2 x0 = *(const float2*)(Xz + (size_t)row0 * 1024 + col);
                float2 x1 = *(const float2*)(Xz + (size_t)row1 * 1024 + col);
                *(float2*)(Cz + (size_t)row0 * 1024 + col) =
                    make_float2(tf32f(s0 * c[i][j][0] + x0.x), tf32f(s0 * c[i][j][1] + x0.y));
                *(float2*)(Cz + (size_t)row1 * 1024 + col) =
                    make_float2(tf32f(s1 * c[i][j][2] + x1.x), tf32f(s1 * c[i][j][3] + x1.y));
            }
        } else {
#pragma unroll
            for (int j = 0; j < 4; j++) {
                const int col = colW + j * 8 + 2 * t;
                const float b0 = bias[col], b1 = bias[col + 1];
                *(float2*)(Cz + (size_t)row0 * 1024 + col) =
                    make_float2(c[i][j][0] + b0, c[i][j][1] + b1);
                *(float2*)(Cz + (size_t)row1 * 1024 + col) =
                    make_float2(c[i][j][2] + b0, c[i][j][3] + b1);
            }
        }
    }
}

// ---------------------------------------------------------------------------
// Tensor-core flash attention half (unchanged from R6, validated)
// ---------------------------------------------------------------------------
#define QP 68
#define VP 72
#define ATT_SMEM ((64 * (3 * QP + VP)) * 4)

__global__ __launch_bounds__(128) void attn_tc(
    const float* __restrict__ Q, const float* __restrict__ K,
    const float* __restrict__ V, const int* __restrict__ mask,
    float* __restrict__ X)
{
    extern __shared__ uint32_t smu[];
    uint32_t* Qs = smu;
    uint32_t* Ks = smu + 64 * QP;
    uint32_t* Ps = smu + 128 * QP;
    uint32_t* Vs = smu + 192 * QP;
    __shared__ int msk[64];

    const int tid = threadIdx.x;
    const int wid = tid >> 5, lane = tid & 31;
    const int g = lane >> 2, t = lane & 3;
    const int b = blockIdx.z, h = blockIdx.y;
    const int q0 = blockIdx.x * 64;

    const float* Qb = Q + ((size_t)b * 1024 + q0) * 1024 + h * 64;
    const float* Kb = K + (size_t)b * 1024 * 1024 + h * 64;
    const float* Vb = V + (size_t)b * 1024 * 1024 + h * 64;
    const int* mb = mask + b * 1024;

    for (int idx = tid; idx < 64 * 16; idx += 128) {
        int r = idx >> 4, c4 = (idx & 15) << 2;
        float4 v = *(const float4*)(Qb + (size_t)r * 1024 + c4);
        uint32_t* d = Qs + r * QP + c4;
        d[0] = __float_as_uint(v.x); d[1] = __float_as_uint(v.y);
        d[2] = __float_as_uint(v.z); d[3] = __float_as_uint(v.w);
    }

    float m0 = -1e30f, m1 = -1e30f, l0 = 0.f, l1 = 0.f;
    float o[8][4];
#pragma unroll
    for (int j = 0; j < 8; j++)
#pragma unroll
        for (int q = 0; q < 4; q++) o[j][q] = 0.f;

    const int rowA = wid * 16 + g;

    for (int kb = 0; kb < 1024; kb += 64) {
        __syncthreads();
        for (int idx = tid; idx < 64 * 16; idx += 128) {
            int r = idx >> 4, c4 = (idx & 15) << 2;
            float4 kv = *(const float4*)(Kb + (size_t)(kb + r) * 1024 + c4);
            uint32_t* dk = Ks + r * QP + c4;
            dk[0] = __float_as_uint(kv.x); dk[1] = __float_as_uint(kv.y);
            dk[2] = __float_as_uint(kv.z); dk[3] = __float_as_uint(kv.w);
            float4 vv = *(const float4*)(Vb + (size_t)(kb + r) * 1024 + c4);
            uint32_t* dv = Vs + r * VP + c4;
            dv[0] = __float_as_uint(vv.x); dv[1] = __float_as_uint(vv.y);
            dv[2] = __float_as_uint(vv.z); dv[3] = __float_as_uint(vv.w);
        }
        if (tid < 64) msk[tid] = mb[kb + tid];
        __syncthreads();

        float s[8][4];
#pragma unroll
        for (int j = 0; j < 8; j++)
#pragma unroll
            for (int q = 0; q < 4; q++) s[j][q] = 0.f;

#pragma unroll
        for (int ks = 0; ks < 8; ks++) {
            uint32_t a[4];
            const uint32_t* ar = Qs + rowA * QP + ks * 8 + t;
            a[0] = ar[0]; a[1] = ar[8 * QP]; a[2] = ar[4]; a[3] = ar[8 * QP + 4];
#pragma unroll
            for (int j = 0; j < 8; j++) {
                uint32_t bb[2];
                const uint32_t* br = Ks + (j * 8 + g) * QP + ks * 8 + t;
                bb[0] = br[0]; bb[1] = br[4];
                mma_tf32(s[j], a, bb);
            }
        }

        float tm0 = -1e30f, tm1 = -1e30f;
#pragma unroll
        for (int j = 0; j < 8; j++) {
            const bool d0 = (msk[j * 8 + 2 * t] == 0);
            const bool d1 = (msk[j * 8 + 2 * t + 1] == 0);
            s[j][0] = d0 ? -1e12f : s[j][0] * 0.125f;
            s[j][1] = d1 ? -1e12f : s[j][1] * 0.125f;
            s[j][2] = d0 ? -1e12f : s[j][2] * 0.125f;
            s[j][3] = d1 ? -1e12f : s[j][3] * 0.125f;
            tm0 = fmaxf(tm0, fmaxf(s[j][0], s[j][1]));
            tm1 = fmaxf(tm1, fmaxf(s[j][2], s[j][3]));
        }
        tm0 = fmaxf(tm0, __shfl_xor_sync(0xffffffffu, tm0, 1));
        tm0 = fmaxf(tm0, __shfl_xor_sync(0xffffffffu, tm0, 2));
        tm1 = fmaxf(tm1, __shfl_xor_sync(0xffffffffu, tm1, 1));
        tm1 = fmaxf(tm1, __shfl_xor_sync(0xffffffffu, tm1, 2));

        const float mn0 = fmaxf(m0, tm0), mn1 = fmaxf(m1, tm1);
        const float al0 = __expf(m0 - mn0), al1 = __expf(m1 - mn1);
        m0 = mn0; m1 = mn1;

        float ts0 = 0.f, ts1 = 0.f;
#pragma unroll
        for (int j = 0; j < 8; j++) {
            s[j][0] = __expf(s[j][0] - mn0);
            s[j][1] = __expf(s[j][1] - mn0);
            s[j][2] = __expf(s[j][2] - mn1);
            s[j][3] = __expf(s[j][3] - mn1);
            ts0 += s[j][0] + s[j][1];
            ts1 += s[j][2] + s[j][3];
        }
        ts0 += __shfl_xor_sync(0xffffffffu, ts0, 1);
        ts0 += __shfl_xor_sync(0xffffffffu, ts0, 2);
        ts1 += __shfl_xor_sync(0xffffffffu, ts1, 1);
        ts1 += __shfl_xor_sync(0xffffffffu, ts1, 2);
        l0 = l0 * al0 + ts0;
        l1 = l1 * al1 + ts1;

#pragma unroll
        for (int j = 0; j < 8; j++) {
            o[j][0] *= al0; o[j][1] *= al0;
            o[j][2] *= al1; o[j][3] *= al1;
        }

#pragma unroll
        for (int j = 0; j < 8; j++) {
            uint32_t* p0 = Ps + rowA * QP + j * 8 + 2 * t;
            uint32_t* p1 = Ps + (rowA + 8) * QP + j * 8 + 2 * t;
            p0[0] = f2tf32(s[j][0]); p0[1] = f2tf32(s[j][1]);
            p1[0] = f2tf32(s[j][2]); p1[1] = f2tf32(s[j][3]);
        }
        __syncwarp();

#pragma unroll
        for (int ks = 0; ks < 8; ks++) {
            uint32_t a[4];
            const uint32_t* ar = Ps + rowA * QP + ks * 8 + t;
            a[0] = ar[0]; a[1] = ar[8 * QP]; a[2] = ar[4]; a[3] = ar[8 * QP + 4];
#pragma unroll
            for (int j = 0; j < 8; j++) {
                uint32_t bb[2];
                const uint32_t* br = Vs + (ks * 8 + t) * VP + j * 8 + g;
                bb[0] = br[0]; bb[1] = br[4 * VP];
                mma_tf32(o[j], a, bb);
            }
        }
    }

    const float sc0 = 0.5f / l0, sc1 = 0.5f / l1;
    float* Xr0 = X + ((size_t)b * 1024 + q0 + rowA) * 1024 + h * 64;
    float* Xr1 = Xr0 + (size_t)8 * 1024;
#pragma unroll
    for (int j = 0; j < 8; j++) {
        *(float2*)(Xr0 + j * 8 + 2 * t) = make_float2(o[j][0] * sc0, o[j][1] * sc0);
        *(float2*)(Xr1 + j * 8 + 2 * t) = make_float2(o[j][2] * sc1, o[j][3] * sc1);
    }
}

// ---------------------------------------------------------------------------
extern "C" void kernel_launch(void* const* d_in, const int* in_sizes, int n_in,
                              void* d_out, int out_size)
{
    const float* query = (const float*)d_in[0];
    const float* key   = (const float*)d_in[1];
    const float* value = (const float*)d_in[2];
    const float* adj   = (const float*)d_in[3];
    const int*   mask  = (const int*)d_in[5];
    const float* Wq = (const float*)d_in[6];
    const float* bq = (const float*)d_in[7];
    const float* Wk = (const float*)d_in[8];
    const float* bk = (const float*)d_in[9];
    const float* Wv = (const float*)d_in[10];
    const float* bv = (const float*)d_in[11];
    const float* Wo = (const float*)d_in[12];
    const float* bo = (const float*)d_in[13];
    float* out = (float*)d_out;

    float *pQ, *pK, *pV, *pX, *pInv, *ptQ, *ptK, *ptV, *ptAdj, *ptW;
    cudaGetSymbolAddress((void**)&pQ, g_Q);
    cudaGetSymbolAddress((void**)&pK, g_K);
    cudaGetSymbolAddress((void**)&pV, g_V);
    cudaGetSymbolAddress((void**)&pX, g_X);
    cudaGetSymbolAddress((void**)&pInv, g_inv);
    cudaGetSymbolAddress((void**)&ptQ, g_tQin);
    cudaGetSymbolAddress((void**)&ptK, g_tKin);
    cudaGetSymbolAddress((void**)&ptV, g_tVin);
    cudaGetSymbolAddress((void**)&ptAdj, g_tAdj);
    cudaGetSymbolAddress((void**)&ptW, g_tW);

    float* ptWq = ptW;
    float* ptWk = ptW + 1024u * 1024u;
    float* ptWv = ptW + 2u * 1024u * 1024u;
    float* ptWo = ptW + 3u * 1024u * 1024u;

    cudaFuncSetAttribute(gemm_tf32, cudaFuncAttributeMaxDynamicSharedMemorySize, GEMM_SMEM);
    cudaFuncSetAttribute(attn_tc, cudaFuncAttributeMaxDynamicSharedMemorySize, ATT_SMEM);

    // (1-4) input conversions
    cvt_tf32<<<8192, 256>>>(query, ptQ);
    cvt_tf32<<<8192, 256>>>(key,   ptK);
    cvt_tf32<<<8192, 256>>>(value, ptV);
    cvt_tf32<<<8192, 256>>>(adj,   ptAdj);
    // (5) all weights
    cvt_w4<<<dim3(1024, 4), 256>>>(Wq, Wk, Wv, Wo, ptW);

    // (6) fused QKV projection  <-- ncu -s 5 -c 1 captures this launch
    {
        GemmArgs a{};
        a.A[0] = ptQ;  a.A[1] = ptK;  a.A[2] = ptV;
        a.B[0] = ptWq; a.B[1] = ptWk; a.B[2] = ptWv;
        a.bias[0] = bq; a.bias[1] = bk; a.bias[2] = bv;
        a.C[0] = pQ; a.C[1] = pK; a.C[2] = pV;
        a.inv = pInv; a.Xin = pX;
        a.sA = a.sB = a.sC = 0;
        a.nsel = 3; a.cmode = 0;
        gemm_tf32<<<dim3(4, 64, 3), 512, GEMM_SMEM>>>(a);
    }

    // (7) rowsum
    rowsum_inv<<<1024, 256>>>(adj, pInv);

    // (8) attention half -> X
    dim3 gAtt(16, 16, 8);
    attn_tc<<<gAtt, 128, ATT_SMEM>>>(pQ, pK, pV, mask, pX);

    // (9) adjacency half: X = tf32(0.5*diag(inv)*(adj@V) + X), batched
    {
        GemmArgs a{};
        a.A[0] = ptAdj; a.B[0] = pV; a.bias[0] = bq /*unused*/; a.C[0] = pX;
        a.inv = pInv; a.Xin = pX;
        a.sA = a.sB = a.sC = (size_t)1024 * 1024;
        a.nsel = 1; a.cmode = 1;
        gemm_tf32<<<dim3(4, 8, 8), 512, GEMM_SMEM>>>(a);
    }

    // (10) output projection (full fp32 store)
    {
        GemmArgs a{};
        a.A[0] = pX; a.B[0] = ptWo; a.bias[0] = bo; a.C[0] = out;
        a.inv = pInv; a.Xin = pX;
        a.sA = a.sB = a.sC = 0;
        a.nsel = 1; a.cmode = 2;
        gemm_tf32<<<dim3(4, 64, 1), 512, GEMM_SMEM>>>(a);
    }
}

// round 8
// speedup vs baseline: 1.0900x; 1.0900x over previous
#include <cuda_runtime.h>
#include <cstdint>

// ============================================================================
// Problem: B=8, N=1024, D=1024, H=16, dk=64
// out = (0.5*softmax(QK^T/8, key-masked) + 0.5*row_norm(adj)) @ V  -> @Wo + bo
// All heavy math on tensor cores via mma.sync tf32; tf32 roundings hoisted.
// R8: GEMM 128x128 block, 4 warps (64x64 warp tile), 2 CTAs/SM, 3-stage.
// ============================================================================

__device__ float g_Q[8u * 1024u * 1024u];
__device__ float g_K[8u * 1024u * 1024u];
__device__ float g_V[8u * 1024u * 1024u];
__device__ float g_X[8u * 1024u * 1024u];
__device__ float g_inv[8u * 1024u];
__device__ float g_tQin[8u * 1024u * 1024u];
__device__ float g_tKin[8u * 1024u * 1024u];
__device__ float g_tVin[8u * 1024u * 1024u];
__device__ float g_tAdj[8u * 1024u * 1024u];
__device__ float g_tW[4u * 1024u * 1024u];   // tf32(Wq|Wk|Wv|Wo)

// ---------------------------------------------------------------------------
__device__ __forceinline__ uint32_t smem_to_u32(const void* p) {
    uint32_t a;
    asm("{ .reg .u64 t; cvta.to.shared.u64 t, %1; cvt.u32.u64 %0, t; }" : "=r"(a) : "l"(p));
    return a;
}
__device__ __forceinline__ void cp_async16(uint32_t s, const void* g) {
    asm volatile("cp.async.cg.shared.global [%0], [%1], 16;" :: "r"(s), "l"(g));
}
#define CP_COMMIT() asm volatile("cp.async.commit_group;" ::: "memory")
#define CP_WAIT(n)  asm volatile("cp.async.wait_group %0;" :: "n"(n) : "memory")

__device__ __forceinline__ uint32_t f2tf32(float x) {
    uint32_t r;
    asm("cvt.rna.tf32.f32 %0, %1;" : "=r"(r) : "f"(x));
    return r;
}
__device__ __forceinline__ float tf32f(float x) {
    return __uint_as_float(f2tf32(x));
}
__device__ __forceinline__ void mma_tf32(float* c, const uint32_t* a, const uint32_t* b) {
    asm volatile(
        "mma.sync.aligned.m16n8k8.row.col.f32.tf32.tf32.f32 "
        "{%0,%1,%2,%3}, {%4,%5,%6,%7}, {%8,%9}, {%0,%1,%2,%3};"
        : "+f"(c[0]), "+f"(c[1]), "+f"(c[2]), "+f"(c[3])
        : "r"(a[0]), "r"(a[1]), "r"(a[2]), "r"(a[3]), "r"(b[0]), "r"(b[1]));
}

// ---------------------------------------------------------------------------
// fp32 -> tf32-valued fp32, elementwise
// ---------------------------------------------------------------------------
__global__ __launch_bounds__(256) void cvt_tf32(
    const float* __restrict__ in, float* __restrict__ out)
{
    int g = blockIdx.x * 256 + threadIdx.x;
    float4 v = ((const float4*)in)[g];
    ((float4*)out)[g] = make_float4(tf32f(v.x), tf32f(v.y), tf32f(v.z), tf32f(v.w));
}

__global__ __launch_bounds__(256) void cvt_w4(
    const float* __restrict__ w0, const float* __restrict__ w1,
    const float* __restrict__ w2, const float* __restrict__ w3,
    float* __restrict__ out)
{
    const float* src = (blockIdx.y == 0) ? w0 : (blockIdx.y == 1) ? w1
                     : (blockIdx.y == 2) ? w2 : w3;
    int g = blockIdx.x * 256 + threadIdx.x;
    float4 v = ((const float4*)src)[g];
    float4* o = (float4*)(out + (size_t)blockIdx.y * 1024u * 1024u);
    o[g] = make_float4(tf32f(v.x), tf32f(v.y), tf32f(v.z), tf32f(v.w));
}

// ---------------------------------------------------------------------------
// adjacency row-sum -> 1/(sum+eps); one warp per row
// ---------------------------------------------------------------------------
__global__ __launch_bounds__(256) void rowsum_inv(
    const float* __restrict__ adj, float* __restrict__ inv)
{
    const int row = blockIdx.x * 8 + (threadIdx.x >> 5);
    const int lane = threadIdx.x & 31;
    const float4* a = (const float4*)(adj + (size_t)row * 1024);
    float s = 0.f;
#pragma unroll
    for (int i = 0; i < 8; i++) {
        float4 v = a[lane + i * 32];
        s += (v.x + v.y) + (v.z + v.w);
    }
#pragma unroll
    for (int o = 16; o > 0; o >>= 1) s += __shfl_xor_sync(0xffffffffu, s, o);
    if (lane == 0) inv[row] = 1.0f / (s + 1e-6f);
}

// ---------------------------------------------------------------------------
// tf32 tensor-core GEMM, cvt-free mainloop.
// 128 threads, 4 warps (2m x 2n), block 128x128, warp 64x64, K-tile 32,
// 3-stage cp.async, 2 CTAs/SM.
// cmode 0: C = tf32(D + bias);  1: C = tf32(0.5*inv*D + Xin);  2: C = D + bias
// ---------------------------------------------------------------------------
#define PA 36
#define PB 136
#define A_STG (128 * PA)             // 4608 floats
#define B_STG (32 * PB)              // 4352 floats
#define STG_STRIDE (A_STG + B_STG)   // 8960 floats
#define NSTG 3
#define GEMM_SMEM (STG_STRIDE * NSTG * 4)   // 107520 bytes

struct GemmArgs {
    const float* A[3];
    const float* B[3];
    const float* bias[3];
    float* C[3];
    const float* inv;
    const float* Xin;
    size_t sA, sB, sC;
    int nsel;
    int cmode;
};

__global__ __launch_bounds__(128, 2) void gemm_tf32(GemmArgs args)
{
    extern __shared__ float sm[];
    const uint32_t base_u = smem_to_u32(sm);

    const int tid = threadIdx.x;
    const int wid = tid >> 5, lane = tid & 31;
    const int wm = wid >> 1, wn = wid & 1;      // 2 x 2 warps
    const int g = lane >> 2, t = lane & 3;

    const int sel = (args.nsel > 1) ? blockIdx.z : 0;
    const int z   = (args.nsel > 1) ? 0 : blockIdx.z;

    const float* Ab = args.A[sel] + (size_t)z * args.sA + (size_t)(blockIdx.y * 128) * 1024;
    const float* Bb = args.B[sel] + (size_t)z * args.sB + blockIdx.x * 128;

    // loaders (128 threads): A 128x32 floats = 1024 f4 (8/thread),
    //                        B 32x128 floats = 1024 f4 (8/thread)
    const int a_r = tid >> 3, a_c4 = (tid & 7) << 2;      // +i*16 rows
    const int b_r = tid >> 5, b_c4 = (tid & 31) << 2;     // +i*4 rows

    float c[4][8][4];
#pragma unroll
    for (int i = 0; i < 4; i++)
#pragma unroll
        for (int j = 0; j < 8; j++)
#pragma unroll
            for (int q = 0; q < 4; q++) c[i][j][q] = 0.f;

    auto load_stage = [&](int kt, int stg) {
        const uint32_t as_u = base_u + (uint32_t)(stg * STG_STRIDE) * 4;
        const uint32_t bs_u = as_u + (uint32_t)A_STG * 4;
#pragma unroll
        for (int i = 0; i < 8; i++) {
            int r = a_r + i * 16;
            cp_async16(as_u + (uint32_t)(r * PA + a_c4) * 4,
                       Ab + (size_t)r * 1024 + kt * 32 + a_c4);
        }
#pragma unroll
        for (int i = 0; i < 8; i++) {
            int r = b_r + i * 4;
            cp_async16(bs_u + (uint32_t)(r * PB + b_c4) * 4,
                       Bb + (size_t)(kt * 32 + r) * 1024 + b_c4);
        }
        CP_COMMIT();
    };

    load_stage(0, 0);
    load_stage(1, 1);

    int stg = 0;
    for (int kt = 0; kt < 32; kt++) {
        if (kt + 2 < 32) { load_stage(kt + 2, (kt + 2) % NSTG); CP_WAIT(2); }
        else if (kt + 1 < 32) { CP_WAIT(1); }
        else { CP_WAIT(0); }
        __syncthreads();

        const uint32_t* Ast = (const uint32_t*)(sm + stg * STG_STRIDE);
        const uint32_t* Bst = Ast + A_STG;
#pragma unroll
        for (int ks = 0; ks < 4; ks++) {
            const int k0 = ks * 8;
            uint32_t af[4][4];
#pragma unroll
            for (int i = 0; i < 4; i++) {
                const uint32_t* ar = Ast + (wm * 64 + i * 16 + g) * PA + k0 + t;
                af[i][0] = ar[0];
                af[i][1] = ar[8 * PA];
                af[i][2] = ar[4];
                af[i][3] = ar[8 * PA + 4];
            }
            uint32_t bf[8][2];
#pragma unroll
            for (int j = 0; j < 8; j++) {
                const uint32_t* br = Bst + (k0 + t) * PB + wn * 64 + j * 8 + g;
                bf[j][0] = br[0];
                bf[j][1] = br[4 * PB];
            }
#pragma unroll
            for (int i = 0; i < 4; i++)
#pragma unroll
                for (int j = 0; j < 8; j++)
                    mma_tf32(c[i][j], af[i], bf[j]);
        }
        __syncthreads();
        stg = (stg + 1) % NSTG;
    }

    // ---- epilogue ----
    const int colW = blockIdx.x * 128 + wn * 64;
    float* Cz = args.C[sel] + (size_t)z * args.sC;
    const float* Xz = args.Xin + (size_t)z * args.sC;
    const float* bias = args.bias[sel];
    const int cmode = args.cmode;

#pragma unroll
    for (int i = 0; i < 4; i++) {
        const int row0 = blockIdx.y * 128 + wm * 64 + i * 16 + g;
        const int row1 = row0 + 8;
        if (cmode == 0) {
#pragma unroll
            for (int j = 0; j < 8; j++) {
                const int col = colW + j * 8 + 2 * t;
                const float b0 = bias[col], b1 = bias[col + 1];
                *(float2*)(Cz + (size_t)row0 * 1024 + col) =
                    make_float2(tf32f(c[i][j][0] + b0), tf32f(c[i][j][1] + b1));
                *(float2*)(Cz + (size_t)row1 * 1024 + col) =
                    make_float2(tf32f(c[i][j][2] + b0), tf32f(c[i][j][3] + b1));
            }
        } else if (cmode == 1) {
            const float s0 = 0.5f * args.inv[z * 1024 + row0];
            const float s1 = 0.5f * args.inv[z * 1024 + row1];
#pragma unroll
            for (int j = 0; j < 8; j++) {
                const int col = colW + j * 8 + 2 * t;
                float2 x0 = *(const float2*)(Xz + (size_t)row0 * 1024 + col);
                float2 x1 = *(const float2*)(Xz + (size_t)row1 * 1024 + col);
                *(float2*)(Cz + (size_t)row0 * 1024 + col) =
                    make_float2(tf32f(s0 * c[i][j][0] + x0.x), tf32f(s0 * c[i][j][1] + x0.y));
                *(float2*)(Cz + (size_t)row1 * 1024 + col) =
                    make_float2(tf32f(s1 * c[i][j][2] + x1.x), tf32f(s1 * c[i][j][3] + x1.y));
            }
        } else {
#pragma unroll
            for (int j = 0; j < 8; j++) {
                const int col = colW + j * 8 + 2 * t;
                const float b0 = bias[col], b1 = bias[col + 1];
                *(float2*)(Cz + (size_t)row0 * 1024 + col) =
                    make_float2(c[i][j][0] + b0, c[i][j][1] + b1);
                *(float2*)(Cz + (size_t)row1 * 1024 + col) =
                    make_float2(c[i][j][2] + b0, c[i][j][3] + b1);
            }
        }
    }
}

// ---------------------------------------------------------------------------
// Tensor-core flash attention half (unchanged, validated)
// ---------------------------------------------------------------------------
#define QP 68
#define VP 72
#define ATT_SMEM ((64 * (3 * QP + VP)) * 4)

__global__ __launch_bounds__(128) void attn_tc(
    const float* __restrict__ Q, const float* __restrict__ K,
    const float* __restrict__ V, const int* __restrict__ mask,
    float* __restrict__ X)
{
    extern __shared__ uint32_t smu[];
    uint32_t* Qs = smu;
    uint32_t* Ks = smu + 64 * QP;
    uint32_t* Ps = smu + 128 * QP;
    uint32_t* Vs = smu + 192 * QP;
    __shared__ int msk[64];

    const int tid = threadIdx.x;
    const int wid = tid >> 5, lane = tid & 31;
    const int g = lane >> 2, t = lane & 3;
    const int b = blockIdx.z, h = blockIdx.y;
    const int q0 = blockIdx.x * 64;

    const float* Qb = Q + ((size_t)b * 1024 + q0) * 1024 + h * 64;
    const float* Kb = K + (size_t)b * 1024 * 1024 + h * 64;
    const float* Vb = V + (size_t)b * 1024 * 1024 + h * 64;
    const int* mb = mask + b * 1024;

    for (int idx = tid; idx < 64 * 16; idx += 128) {
        int r = idx >> 4, c4 = (idx & 15) << 2;
        float4 v = *(const float4*)(Qb + (size_t)r * 1024 + c4);
        uint32_t* d = Qs + r * QP + c4;
        d[0] = __float_as_uint(v.x); d[1] = __float_as_uint(v.y);
        d[2] = __float_as_uint(v.z); d[3] = __float_as_uint(v.w);
    }

    float m0 = -1e30f, m1 = -1e30f, l0 = 0.f, l1 = 0.f;
    float o[8][4];
#pragma unroll
    for (int j = 0; j < 8; j++)
#pragma unroll
        for (int q = 0; q < 4; q++) o[j][q] = 0.f;

    const int rowA = wid * 16 + g;

    for (int kb = 0; kb < 1024; kb += 64) {
        __syncthreads();
        for (int idx = tid; idx < 64 * 16; idx += 128) {
            int r = idx >> 4, c4 = (idx & 15) << 2;
            float4 kv = *(const float4*)(Kb + (size_t)(kb + r) * 1024 + c4);
            uint32_t* dk = Ks + r * QP + c4;
            dk[0] = __float_as_uint(kv.x); dk[1] = __float_as_uint(kv.y);
            dk[2] = __float_as_uint(kv.z); dk[3] = __float_as_uint(kv.w);
            float4 vv = *(const float4*)(Vb + (size_t)(kb + r) * 1024 + c4);
            uint32_t* dv = Vs + r * VP + c4;
            dv[0] = __float_as_uint(vv.x); dv[1] = __float_as_uint(vv.y);
            dv[2] = __float_as_uint(vv.z); dv[3] = __float_as_uint(vv.w);
        }
        if (tid < 64) msk[tid] = mb[kb + tid];
        __syncthreads();

        float s[8][4];
#pragma unroll
        for (int j = 0; j < 8; j++)
#pragma unroll
            for (int q = 0; q < 4; q++) s[j][q] = 0.f;

#pragma unroll
        for (int ks = 0; ks < 8; ks++) {
            uint32_t a[4];
            const uint32_t* ar = Qs + rowA * QP + ks * 8 + t;
            a[0] = ar[0]; a[1] = ar[8 * QP]; a[2] = ar[4]; a[3] = ar[8 * QP + 4];
#pragma unroll
            for (int j = 0; j < 8; j++) {
                uint32_t bb[2];
                const uint32_t* br = Ks + (j * 8 + g) * QP + ks * 8 + t;
                bb[0] = br[0]; bb[1] = br[4];
                mma_tf32(s[j], a, bb);
            }
        }

        float tm0 = -1e30f, tm1 = -1e30f;
#pragma unroll
        for (int j = 0; j < 8; j++) {
            const bool d0 = (msk[j * 8 + 2 * t] == 0);
            const bool d1 = (msk[j * 8 + 2 * t + 1] == 0);
            s[j][0] = d0 ? -1e12f : s[j][0] * 0.125f;
            s[j][1] = d1 ? -1e12f : s[j][1] * 0.125f;
            s[j][2] = d0 ? -1e12f : s[j][2] * 0.125f;
            s[j][3] = d1 ? -1e12f : s[j][3] * 0.125f;
            tm0 = fmaxf(tm0, fmaxf(s[j][0], s[j][1]));
            tm1 = fmaxf(tm1, fmaxf(s[j][2], s[j][3]));
        }
        tm0 = fmaxf(tm0, __shfl_xor_sync(0xffffffffu, tm0, 1));
        tm0 = fmaxf(tm0, __shfl_xor_sync(0xffffffffu, tm0, 2));
        tm1 = fmaxf(tm1, __shfl_xor_sync(0xffffffffu, tm1, 1));
        tm1 = fmaxf(tm1, __shfl_xor_sync(0xffffffffu, tm1, 2));

        const float mn0 = fmaxf(m0, tm0), mn1 = fmaxf(m1, tm1);
        const float al0 = __expf(m0 - mn0), al1 = __expf(m1 - mn1);
        m0 = mn0; m1 = mn1;

        float ts0 = 0.f, ts1 = 0.f;
#pragma unroll
        for (int j = 0; j < 8; j++) {
            s[j][0] = __expf(s[j][0] - mn0);
            s[j][1] = __expf(s[j][1] - mn0);
            s[j][2] = __expf(s[j][2] - mn1);
            s[j][3] = __expf(s[j][3] - mn1);
            ts0 += s[j][0] + s[j][1];
            ts1 += s[j][2] + s[j][3];
        }
        ts0 += __shfl_xor_sync(0xffffffffu, ts0, 1);
        ts0 += __shfl_xor_sync(0xffffffffu, ts0, 2);
        ts1 += __shfl_xor_sync(0xffffffffu, ts1, 1);
        ts1 += __shfl_xor_sync(0xffffffffu, ts1, 2);
        l0 = l0 * al0 + ts0;
        l1 = l1 * al1 + ts1;

#pragma unroll
        for (int j = 0; j < 8; j++) {
            o[j][0] *= al0; o[j][1] *= al0;
            o[j][2] *= al1; o[j][3] *= al1;
        }

#pragma unroll
        for (int j = 0; j < 8; j++) {
            uint32_t* p0 = Ps + rowA * QP + j * 8 + 2 * t;
            uint32_t* p1 = Ps + (rowA + 8) * QP + j * 8 + 2 * t;
            p0[0] = f2tf32(s[j][0]); p0[1] = f2tf32(s[j][1]);
            p1[0] = f2tf32(s[j][2]); p1[1] = f2tf32(s[j][3]);
        }
        __syncwarp();

#pragma unroll
        for (int ks = 0; ks < 8; ks++) {
            uint32_t a[4];
            const uint32_t* ar = Ps + rowA * QP + ks * 8 + t;
            a[0] = ar[0]; a[1] = ar[8 * QP]; a[2] = ar[4]; a[3] = ar[8 * QP + 4];
#pragma unroll
            for (int j = 0; j < 8; j++) {
                uint32_t bb[2];
                const uint32_t* br = Vs + (ks * 8 + t) * VP + j * 8 + g;
                bb[0] = br[0]; bb[1] = br[4 * VP];
                mma_tf32(o[j], a, bb);
            }
        }
    }

    const float sc0 = 0.5f / l0, sc1 = 0.5f / l1;
    float* Xr0 = X + ((size_t)b * 1024 + q0 + rowA) * 1024 + h * 64;
    float* Xr1 = Xr0 + (size_t)8 * 1024;
#pragma unroll
    for (int j = 0; j < 8; j++) {
        *(float2*)(Xr0 + j * 8 + 2 * t) = make_float2(o[j][0] * sc0, o[j][1] * sc0);
        *(float2*)(Xr1 + j * 8 + 2 * t) = make_float2(o[j][2] * sc1, o[j][3] * sc1);
    }
}

// ---------------------------------------------------------------------------
extern "C" void kernel_launch(void* const* d_in, const int* in_sizes, int n_in,
                              void* d_out, int out_size)
{
    const float* query = (const float*)d_in[0];
    const float* key   = (const float*)d_in[1];
    const float* value = (const float*)d_in[2];
    const float* adj   = (const float*)d_in[3];
    const int*   mask  = (const int*)d_in[5];
    const float* Wq = (const float*)d_in[6];
    const float* bq = (const float*)d_in[7];
    const float* Wk = (const float*)d_in[8];
    const float* bk = (const float*)d_in[9];
    const float* Wv = (const float*)d_in[10];
    const float* bv = (const float*)d_in[11];
    const float* Wo = (const float*)d_in[12];
    const float* bo = (const float*)d_in[13];
    float* out = (float*)d_out;

    float *pQ, *pK, *pV, *pX, *pInv, *ptQ, *ptK, *ptV, *ptAdj, *ptW;
    cudaGetSymbolAddress((void**)&pQ, g_Q);
    cudaGetSymbolAddress((void**)&pK, g_K);
    cudaGetSymbolAddress((void**)&pV, g_V);
    cudaGetSymbolAddress((void**)&pX, g_X);
    cudaGetSymbolAddress((void**)&pInv, g_inv);
    cudaGetSymbolAddress((void**)&ptQ, g_tQin);
    cudaGetSymbolAddress((void**)&ptK, g_tKin);
    cudaGetSymbolAddress((void**)&ptV, g_tVin);
    cudaGetSymbolAddress((void**)&ptAdj, g_tAdj);
    cudaGetSymbolAddress((void**)&ptW, g_tW);

    float* ptWq = ptW;
    float* ptWk = ptW + 1024u * 1024u;
    float* ptWv = ptW + 2u * 1024u * 1024u;
    float* ptWo = ptW + 3u * 1024u * 1024u;

    cudaFuncSetAttribute(gemm_tf32, cudaFuncAttributeMaxDynamicSharedMemorySize, GEMM_SMEM);
    cudaFuncSetAttribute(attn_tc, cudaFuncAttributeMaxDynamicSharedMemorySize, ATT_SMEM);

    // input conversions
    cvt_tf32<<<8192, 256>>>(query, ptQ);
    cvt_tf32<<<8192, 256>>>(key,   ptK);
    cvt_tf32<<<8192, 256>>>(value, ptV);
    cvt_tf32<<<8192, 256>>>(adj,   ptAdj);
    cvt_w4<<<dim3(1024, 4), 256>>>(Wq, Wk, Wv, Wo, ptW);

    // fused QKV projection
    {
        GemmArgs a{};
        a.A[0] = ptQ;  a.A[1] = ptK;  a.A[2] = ptV;
        a.B[0] = ptWq; a.B[1] = ptWk; a.B[2] = ptWv;
        a.bias[0] = bq; a.bias[1] = bk; a.bias[2] = bv;
        a.C[0] = pQ; a.C[1] = pK; a.C[2] = pV;
        a.inv = pInv; a.Xin = pX;
        a.sA = a.sB = a.sC = 0;
        a.nsel = 3; a.cmode = 0;
        gemm_tf32<<<dim3(8, 64, 3), 128, GEMM_SMEM>>>(a);
    }

    rowsum_inv<<<1024, 256>>>(adj, pInv);

    // attention half -> X
    dim3 gAtt(16, 16, 8);
    attn_tc<<<gAtt, 128, ATT_SMEM>>>(pQ, pK, pV, mask, pX);

    // adjacency half: X = tf32(0.5*diag(inv)*(adj@V) + X), batched
    {
        GemmArgs a{};
        a.A[0] = ptAdj; a.B[0] = pV; a.bias[0] = bq /*unused*/; a.C[0] = pX;
        a.inv = pInv; a.Xin = pX;
        a.sA = a.sB = a.sC = (size_t)1024 * 1024;
        a.nsel = 1; a.cmode = 1;
        gemm_tf32<<<dim3(8, 8, 8), 128, GEMM_SMEM>>>(a);
    }

    // output projection (full fp32 store)
    {
        GemmArgs a{};
        a.A[0] = pX; a.B[0] = ptWo; a.bias[0] = bo; a.C[0] = out;
        a.inv = pInv; a.Xin = pX;
        a.sA = a.sB = a.sC = 0;
        a.nsel = 1; a.cmode = 2;
        gemm_tf32<<<dim3(8, 64, 1), 128, GEMM_SMEM>>>(a);
    }
}

// round 9
// speedup vs baseline: 1.4828x; 1.3603x over previous
#include <cuda_runtime.h>
#include <cuda_fp16.h>
#include <cstdint>

// ============================================================================
// Problem: B=8, N=1024, D=1024, H=16, dk=64
// out = (0.5*softmax(QK^T/8, key-masked) + 0.5*row_norm(adj)) @ V  -> @Wo + bo
// All heavy math via mma.sync m16n8k16 fp16 (same 10-bit mantissa as tf32,
// 2x MACs/instr, half the LDS + staging traffic). fp32 accumulate throughout.
// B-operands use k-paired word layout: word = (B[2k][n], B[2k+1][n]).
// ============================================================================

__device__ __half   g_Q16[8u * 1024u * 1024u];
__device__ __half   g_K16[8u * 1024u * 1024u];
__device__ __half   g_V16[8u * 1024u * 1024u];
__device__ __half   g_X16[8u * 1024u * 1024u];
__device__ __half   g_in16[4u * 8u * 1024u * 1024u];   // q|k|v|adj fp16
__device__ uint32_t g_Wp[4u * 512u * 1024u];           // k-paired Wq|Wk|Wv|Wo
__device__ uint32_t g_Vp[8u * 512u * 1024u];           // k-paired V per batch
__device__ float    g_inv[8u * 1024u];

// ---------------------------------------------------------------------------
__device__ __forceinline__ uint32_t smem_to_u32(const void* p) {
    uint32_t a;
    asm("{ .reg .u64 t; cvta.to.shared.u64 t, %1; cvt.u32.u64 %0, t; }" : "=r"(a) : "l"(p));
    return a;
}
__device__ __forceinline__ void cp_async16(uint32_t s, const void* g) {
    asm volatile("cp.async.cg.shared.global [%0], [%1], 16;" :: "r"(s), "l"(g));
}
#define CP_COMMIT() asm volatile("cp.async.commit_group;" ::: "memory")
#define CP_WAIT(n)  asm volatile("cp.async.wait_group %0;" :: "n"(n) : "memory")

__device__ __forceinline__ void mma_fp16(float* c, const uint32_t* a, const uint32_t* b) {
    asm volatile(
        "mma.sync.aligned.m16n8k16.row.col.f32.f16.f16.f32 "
        "{%0,%1,%2,%3}, {%4,%5,%6,%7}, {%8,%9}, {%0,%1,%2,%3};"
        : "+f"(c[0]), "+f"(c[1]), "+f"(c[2]), "+f"(c[3])
        : "r"(a[0]), "r"(a[1]), "r"(a[2]), "r"(a[3]), "r"(b[0]), "r"(b[1]));
}
__device__ __forceinline__ uint32_t pack_h2(float lo, float hi) {
    __half2 h = __floats2half2_rn(lo, hi);
    return *(uint32_t*)&h;
}

// ---------------------------------------------------------------------------
// inputs (q,k,v,adj) fp32 -> fp16; grid (4096, 4), 8 elems/thread
// ---------------------------------------------------------------------------
__global__ __launch_bounds__(256) void cvt_in4(
    const float* __restrict__ q, const float* __restrict__ k,
    const float* __restrict__ v, const float* __restrict__ adj,
    __half* __restrict__ out)
{
    const float* src = (blockIdx.y == 0) ? q : (blockIdx.y == 1) ? k
                     : (blockIdx.y == 2) ? v : adj;
    size_t idx = (size_t)blockIdx.x * 256 + threadIdx.x;   // 8-elem chunk
    float4 a = ((const float4*)src)[idx * 2];
    float4 b = ((const float4*)src)[idx * 2 + 1];
    uint4 o;
    o.x = pack_h2(a.x, a.y); o.y = pack_h2(a.z, a.w);
    o.z = pack_h2(b.x, b.y); o.w = pack_h2(b.z, b.w);
    ((uint4*)(out + (size_t)blockIdx.y * 8u * 1024u * 1024u))[idx] = o;
}

// weights fp32 [k][n] -> k-paired fp16 words Wp[k2][n]; grid (512, 4)
__global__ __launch_bounds__(256) void cvt_wp(
    const float* __restrict__ w0, const float* __restrict__ w1,
    const float* __restrict__ w2, const float* __restrict__ w3,
    uint32_t* __restrict__ out)
{
    const float* W = (blockIdx.y == 0) ? w0 : (blockIdx.y == 1) ? w1
                   : (blockIdx.y == 2) ? w2 : w3;
    int idx = blockIdx.x * 256 + threadIdx.x;   // 4-word chunk
    int k2 = (idx * 4) >> 10;
    int n  = (idx * 4) & 1023;
    float4 wa = *(const float4*)(W + (size_t)(2 * k2) * 1024 + n);
    float4 wb = *(const float4*)(W + (size_t)(2 * k2 + 1) * 1024 + n);
    uint4 o;
    o.x = pack_h2(wa.x, wb.x); o.y = pack_h2(wa.y, wb.y);
    o.z = pack_h2(wa.z, wb.z); o.w = pack_h2(wa.w, wb.w);
    *(uint4*)(out + (size_t)blockIdx.y * 512u * 1024u + idx * 4) = o;
}

// V fp16 [b][tok][n] -> k-paired Vp[b][tok2][n]; 8 words/thread
__global__ __launch_bounds__(256) void pairV(
    const __half* __restrict__ V, uint32_t* __restrict__ Vp)
{
    size_t w = ((size_t)blockIdx.x * 256 + threadIdx.x) * 8;
    size_t b = w >> 19;
    size_t rem = w & ((512u * 1024u) - 1);
    size_t k2 = rem >> 10;
    size_t n = rem & 1023;
    const __half* ra = V + (b * 1024 + 2 * k2) * 1024 + n;
    const __half* rb = ra + 1024;
    uint4 va = *(const uint4*)ra;
    uint4 vb = *(const uint4*)rb;
    const __half* ha = (const __half*)&va;
    const __half* hb = (const __half*)&vb;
    uint4 o0, o1;
    uint32_t* po0 = (uint32_t*)&o0;
    uint32_t* po1 = (uint32_t*)&o1;
#pragma unroll
    for (int i = 0; i < 4; i++) {
        __half2 p = __halves2half2(ha[i], hb[i]);
        po0[i] = *(uint32_t*)&p;
    }
#pragma unroll
    for (int i = 0; i < 4; i++) {
        __half2 p = __halves2half2(ha[4 + i], hb[4 + i]);
        po1[i] = *(uint32_t*)&p;
    }
    uint32_t* dst = Vp + b * 512 * 1024 + k2 * 1024 + n;
    *(uint4*)dst = o0;
    *(uint4*)(dst + 4) = o1;
}

// ---------------------------------------------------------------------------
// adjacency row-sum -> 1/(sum+eps); one warp per row (fp32 source)
// ---------------------------------------------------------------------------
__global__ __launch_bounds__(256) void rowsum_inv(
    const float* __restrict__ adj, float* __restrict__ inv)
{
    const int row = blockIdx.x * 8 + (threadIdx.x >> 5);
    const int lane = threadIdx.x & 31;
    const float4* a = (const float4*)(adj + (size_t)row * 1024);
    float s = 0.f;
#pragma unroll
    for (int i = 0; i < 8; i++) {
        float4 v = a[lane + i * 32];
        s += (v.x + v.y) + (v.z + v.w);
    }
#pragma unroll
    for (int o = 16; o > 0; o >>= 1) s += __shfl_xor_sync(0xffffffffu, s, o);
    if (lane == 0) inv[row] = 1.0f / (s + 1e-6f);
}

// ---------------------------------------------------------------------------
// fp16 tensor-core GEMM: C[M,1024] = A[M,1024] @ B[1024,1024]
// A fp16 row-major; B k-paired words. 128 threads, 4 warps (2x2),
// block 128x128, warp 64x64, k-tile 32, 4-stage cp.async, 2 CTAs/SM.
// cmode 0: C(fp16) = D + bias;  1: C(fp16) = 0.5*inv*D + Xin(fp16);
// cmode 2: C(fp32) = D + bias
// ---------------------------------------------------------------------------
#define PA16 20                      // A smem pitch (words)
#define PB16 136                     // B smem pitch (words)
#define A_STG (128 * PA16)           // 2560 words
#define B_STG (16 * PB16)            // 2176 words
#define STG_STRIDE (A_STG + B_STG)   // 4736 words
#define NSTG 4
#define GEMM_SMEM (STG_STRIDE * NSTG * 4)   // 75776 bytes

struct GemmArgs {
    const __half* A[3];
    const uint32_t* B[3];
    const float* bias[3];
    void* C[3];
    const float* inv;
    const __half* Xin;
    size_t sA, sB, sC;     // per-batch strides: halves / words / elements
    int nsel;
    int cmode;
};

__global__ __launch_bounds__(128, 2) void gemm_fp16(GemmArgs args)
{
    extern __shared__ uint32_t smw[];
    const uint32_t base_u = smem_to_u32(smw);

    const int tid = threadIdx.x;
    const int wid = tid >> 5, lane = tid & 31;
    const int wm = wid >> 1, wn = wid & 1;
    const int g = lane >> 2, t = lane & 3;

    const int sel = (args.nsel > 1) ? blockIdx.z : 0;
    const int z   = (args.nsel > 1) ? 0 : blockIdx.z;

    const __half* Ab = args.A[sel] + (size_t)z * args.sA + (size_t)(blockIdx.y * 128) * 1024;
    const uint32_t* Bb = args.B[sel] + (size_t)z * args.sB + blockIdx.x * 128;

    const int a_r = tid >> 2, a_cw = (tid & 3) * 4;     // +i*32 rows, word col
    const int b_r = tid >> 5, b_cw = (tid & 31) * 4;    // +i*4 rows

    float c[4][8][4];
#pragma unroll
    for (int i = 0; i < 4; i++)
#pragma unroll
        for (int j = 0; j < 8; j++)
#pragma unroll
            for (int q = 0; q < 4; q++) c[i][j][q] = 0.f;

    auto load_stage = [&](int kt, int stg) {
        const uint32_t as_u = base_u + (uint32_t)(stg * STG_STRIDE) * 4;
        const uint32_t bs_u = as_u + (uint32_t)A_STG * 4;
#pragma unroll
        for (int i = 0; i < 4; i++) {
            int r = a_r + i * 32;
            cp_async16(as_u + (uint32_t)(r * PA16 + a_cw) * 4,
                       Ab + (size_t)r * 1024 + kt * 32 + a_cw * 2);
        }
#pragma unroll
        for (int i = 0; i < 4; i++) {
            int r = b_r + i * 4;
            cp_async16(bs_u + (uint32_t)(r * PB16 + b_cw) * 4,
                       Bb + (size_t)(kt * 16 + r) * 1024 + b_cw);
        }
        CP_COMMIT();
    };

    load_stage(0, 0);
    load_stage(1, 1);
    load_stage(2, 2);

    int stg = 0;
    for (int kt = 0; kt < 32; kt++) {
        if (kt + 3 < 32) { load_stage(kt + 3, (kt + 3) & (NSTG - 1)); CP_WAIT(3); }
        else { CP_WAIT(0); }
        __syncthreads();

        const uint32_t* Ast = smw + stg * STG_STRIDE;
        const uint32_t* Bst = Ast + A_STG;
#pragma unroll
        for (int ks = 0; ks < 2; ks++) {
            uint32_t af[4][4];
#pragma unroll
            for (int i = 0; i < 4; i++) {
                const uint32_t* ar = Ast + (wm * 64 + i * 16 + g) * PA16 + ks * 8 + t;
                af[i][0] = ar[0];
                af[i][1] = ar[8 * PA16];
                af[i][2] = ar[4];
                af[i][3] = ar[8 * PA16 + 4];
            }
            uint32_t bf[8][2];
#pragma unroll
            for (int j = 0; j < 8; j++) {
                const uint32_t* br = Bst + (ks * 8 + t) * PB16 + wn * 64 + j * 8 + g;
                bf[j][0] = br[0];
                bf[j][1] = br[4 * PB16];
            }
#pragma unroll
            for (int i = 0; i < 4; i++)
#pragma unroll
                for (int j = 0; j < 8; j++)
                    mma_fp16(c[i][j], af[i], bf[j]);
        }
        __syncthreads();
        stg = (stg + 1) & (NSTG - 1);
    }

    // ---- epilogue ----
    const int colW = blockIdx.x * 128 + wn * 64;
    const float* bias = args.bias[sel];
    const int cmode = args.cmode;

#pragma unroll
    for (int i = 0; i < 4; i++) {
        const int row0 = blockIdx.y * 128 + wm * 64 + i * 16 + g;
        const int row1 = row0 + 8;
        if (cmode == 0) {
            __half2* C16 = (__half2*)args.C[sel];
#pragma unroll
            for (int j = 0; j < 8; j++) {
                const int col = colW + j * 8 + 2 * t;
                const float b0 = bias[col], b1 = bias[col + 1];
                C16[(size_t)row0 * 512 + (col >> 1)] =
                    __floats2half2_rn(c[i][j][0] + b0, c[i][j][1] + b1);
                C16[(size_t)row1 * 512 + (col >> 1)] =
                    __floats2half2_rn(c[i][j][2] + b0, c[i][j][3] + b1);
            }
        } else if (cmode == 1) {
            __half2* C16 = (__half2*)args.C[0] + (size_t)z * (args.sC >> 1);
            const __half2* X16 = (const __half2*)args.Xin + (size_t)z * (args.sC >> 1);
            const float s0 = 0.5f * args.inv[z * 1024 + row0];
            const float s1 = 0.5f * args.inv[z * 1024 + row1];
#pragma unroll
            for (int j = 0; j < 8; j++) {
                const int col = colW + j * 8 + 2 * t;
                float2 x0 = __half22float2(X16[(size_t)row0 * 512 + (col >> 1)]);
                float2 x1 = __half22float2(X16[(size_t)row1 * 512 + (col >> 1)]);
                C16[(size_t)row0 * 512 + (col >> 1)] =
                    __floats2half2_rn(s0 * c[i][j][0] + x0.x, s0 * c[i][j][1] + x0.y);
                C16[(size_t)row1 * 512 + (col >> 1)] =
                    __floats2half2_rn(s1 * c[i][j][2] + x1.x, s1 * c[i][j][3] + x1.y);
            }
        } else {
            float* Cf = (float*)args.C[0];
#pragma unroll
            for (int j = 0; j < 8; j++) {
                const int col = colW + j * 8 + 2 * t;
                const float b0 = bias[col], b1 = bias[col + 1];
                *(float2*)(Cf + (size_t)row0 * 1024 + col) =
                    make_float2(c[i][j][0] + b0, c[i][j][1] + b1);
                *(float2*)(Cf + (size_t)row1 * 1024 + col) =
                    make_float2(c[i][j][2] + b0, c[i][j][3] + b1);
            }
        }
    }
}

// ---------------------------------------------------------------------------
// fp16 tensor-core flash attention half:
// X16[b,q,h*64+d] = fp16( 0.5 * softmax(QK^T/8, key-masked) @ V )
// Block = 64 queries of one (b,h); 4 warps x 16 q-rows. m16n8k16 fp16.
// Qs/Ks: fp16 [row][64] as words pitch 36. Ps staged fp16. Vs from k-paired Vp.
// ---------------------------------------------------------------------------
#define QP16 36   // pitch (words) for Qs/Ks/Ps
#define VP16 72   // pitch (words) for Vs
#define ATT_SMEM ((3 * 64 * QP16 + 32 * VP16) * 4)   // 36864 bytes

__global__ __launch_bounds__(128) void attn_fp16(
    const __half* __restrict__ Q, const __half* __restrict__ K,
    const uint32_t* __restrict__ Vp, const int* __restrict__ mask,
    __half* __restrict__ X)
{
    extern __shared__ uint32_t smu[];
    uint32_t* Qs = smu;                    // [64][QP16]
    uint32_t* Ks = smu + 64 * QP16;
    uint32_t* Ps = smu + 128 * QP16;
    uint32_t* Vs = smu + 192 * QP16;       // [32][VP16]
    __shared__ int msk[64];

    const int tid = threadIdx.x;
    const int wid = tid >> 5, lane = tid & 31;
    const int g = lane >> 2, t = lane & 3;
    const int b = blockIdx.z, h = blockIdx.y;
    const int q0 = blockIdx.x * 64;

    const __half* Qb = Q + ((size_t)b * 1024 + q0) * 1024 + h * 64;
    const __half* Kb = K + (size_t)b * 1024 * 1024 + h * 64;
    const uint32_t* Vpb = Vp + (size_t)b * 512 * 1024 + h * 64;
    const int* mb = mask + b * 1024;

    // Q tile: 64 rows x 32 words (8 uint4/row)
    for (int idx = tid; idx < 512; idx += 128) {
        int r = idx >> 3, c = (idx & 7) * 4;
        *(uint4*)(Qs + r * QP16 + c) = *(const uint4*)(Qb + (size_t)r * 1024 + c * 2);
    }

    float m0 = -1e30f, m1 = -1e30f, l0 = 0.f, l1 = 0.f;
    float o[8][4];
#pragma unroll
    for (int j = 0; j < 8; j++)
#pragma unroll
        for (int q = 0; q < 4; q++) o[j][q] = 0.f;

    const int rowA = wid * 16 + g;

    for (int kb = 0; kb < 1024; kb += 64) {
        __syncthreads();
        for (int idx = tid; idx < 512; idx += 128) {
            int r = idx >> 3, c = (idx & 7) * 4;
            *(uint4*)(Ks + r * QP16 + c) =
                *(const uint4*)(Kb + (size_t)(kb + r) * 1024 + c * 2);
        }
        // V tile: 32 k2-rows x 64 words (16 uint4/row)
        for (int idx = tid; idx < 512; idx += 128) {
            int r = idx >> 4, c = (idx & 15) * 4;
            *(uint4*)(Vs + r * VP16 + c) =
                *(const uint4*)(Vpb + (size_t)((kb >> 1) + r) * 1024 + c);
        }
        if (tid < 64) msk[tid] = mb[kb + tid];
        __syncthreads();

        // ---- S = Q K^T : 4 ks-steps over d ----
        float s[8][4];
#pragma unroll
        for (int j = 0; j < 8; j++)
#pragma unroll
            for (int q = 0; q < 4; q++) s[j][q] = 0.f;

#pragma unroll
        for (int ks = 0; ks < 4; ks++) {
            uint32_t a[4];
            const uint32_t* ar = Qs + rowA * QP16 + ks * 8 + t;
            a[0] = ar[0]; a[1] = ar[8 * QP16]; a[2] = ar[4]; a[3] = ar[8 * QP16 + 4];
#pragma unroll
            for (int j = 0; j < 8; j++) {
                uint32_t bb[2];
                const uint32_t* br = Ks + (j * 8 + g) * QP16 + ks * 8 + t;
                bb[0] = br[0]; bb[1] = br[4];
                mma_fp16(s[j], a, bb);
            }
        }

        // ---- scale + mask; online softmax (layout same as before) ----
        float tm0 = -1e30f, tm1 = -1e30f;
#pragma unroll
        for (int j = 0; j < 8; j++) {
            const bool d0 = (msk[j * 8 + 2 * t] == 0);
            const bool d1 = (msk[j * 8 + 2 * t + 1] == 0);
            s[j][0] = d0 ? -1e12f : s[j][0] * 0.125f;
            s[j][1] = d1 ? -1e12f : s[j][1] * 0.125f;
            s[j][2] = d0 ? -1e12f : s[j][2] * 0.125f;
            s[j][3] = d1 ? -1e12f : s[j][3] * 0.125f;
            tm0 = fmaxf(tm0, fmaxf(s[j][0], s[j][1]));
            tm1 = fmaxf(tm1, fmaxf(s[j][2], s[j][3]));
        }
        tm0 = fmaxf(tm0, __shfl_xor_sync(0xffffffffu, tm0, 1));
        tm0 = fmaxf(tm0, __shfl_xor_sync(0xffffffffu, tm0, 2));
        tm1 = fmaxf(tm1, __shfl_xor_sync(0xffffffffu, tm1, 1));
        tm1 = fmaxf(tm1, __shfl_xor_sync(0xffffffffu, tm1, 2));

        const float mn0 = fmaxf(m0, tm0), mn1 = fmaxf(m1, tm1);
        const float al0 = __expf(m0 - mn0), al1 = __expf(m1 - mn1);
        m0 = mn0; m1 = mn1;

        float ts0 = 0.f, ts1 = 0.f;
#pragma unroll
        for (int j = 0; j < 8; j++) {
            s[j][0] = __expf(s[j][0] - mn0);
            s[j][1] = __expf(s[j][1] - mn0);
            s[j][2] = __expf(s[j][2] - mn1);
            s[j][3] = __expf(s[j][3] - mn1);
            ts0 += s[j][0] + s[j][1];
            ts1 += s[j][2] + s[j][3];
        }
        ts0 += __shfl_xor_sync(0xffffffffu, ts0, 1);
        ts0 += __shfl_xor_sync(0xffffffffu, ts0, 2);
        ts1 += __shfl_xor_sync(0xffffffffu, ts1, 1);
        ts1 += __shfl_xor_sync(0xffffffffu, ts1, 2);
        l0 = l0 * al0 + ts0;
        l1 = l1 * al1 + ts1;

#pragma unroll
        for (int j = 0; j < 8; j++) {
            o[j][0] *= al0; o[j][1] *= al0;
            o[j][2] *= al1; o[j][3] *= al1;
        }

        // ---- stage P as fp16 pairs (adjacent keys) ----
#pragma unroll
        for (int j = 0; j < 8; j++) {
            Ps[rowA * QP16 + j * 4 + t]       = pack_h2(s[j][0], s[j][1]);
            Ps[(rowA + 8) * QP16 + j * 4 + t] = pack_h2(s[j][2], s[j][3]);
        }
        __syncwarp();

        // ---- O += P V : 4 ks-steps over keys ----
#pragma unroll
        for (int ks = 0; ks < 4; ks++) {
            uint32_t a[4];
            const uint32_t* ar = Ps + rowA * QP16 + ks * 8 + t;
            a[0] = ar[0]; a[1] = ar[8 * QP16]; a[2] = ar[4]; a[3] = ar[8 * QP16 + 4];
#pragma unroll
            for (int j = 0; j < 8; j++) {
                uint32_t bb[2];
                const uint32_t* br = Vs + (ks * 8 + t) * VP16 + j * 8 + g;
                bb[0] = br[0]; bb[1] = br[4 * VP16];
                mma_fp16(o[j], a, bb);
            }
        }
    }

    // ---- epilogue: X16 = fp16(0.5 * O / l) ----
    const float sc0 = 0.5f / l0, sc1 = 0.5f / l1;
    __half2* Xr0 = (__half2*)X + ((size_t)b * 1024 + q0 + rowA) * 512 + h * 32;
    __half2* Xr1 = Xr0 + (size_t)8 * 512;
#pragma unroll
    for (int j = 0; j < 8; j++) {
        Xr0[j * 4 + t] = __floats2half2_rn(o[j][0] * sc0, o[j][1] * sc0);
        Xr1[j * 4 + t] = __floats2half2_rn(o[j][2] * sc1, o[j][3] * sc1);
    }
}

// ---------------------------------------------------------------------------
extern "C" void kernel_launch(void* const* d_in, const int* in_sizes, int n_in,
                              void* d_out, int out_size)
{
    const float* query = (const float*)d_in[0];
    const float* key   = (const float*)d_in[1];
    const float* value = (const float*)d_in[2];
    const float* adj   = (const float*)d_in[3];
    const int*   mask  = (const int*)d_in[5];
    const float* Wq = (const float*)d_in[6];
    const float* bq = (const float*)d_in[7];
    const float* Wk = (const float*)d_in[8];
    const float* bk = (const float*)d_in[9];
    const float* Wv = (const float*)d_in[10];
    const float* bv = (const float*)d_in[11];
    const float* Wo = (const float*)d_in[12];
    const float* bo = (const float*)d_in[13];
    float* out = (float*)d_out;

    __half *pQ, *pK, *pV, *pX, *pIn;
    uint32_t *pWp, *pVp;
    float *pInv;
    cudaGetSymbolAddress((void**)&pQ, g_Q16);
    cudaGetSymbolAddress((void**)&pK, g_K16);
    cudaGetSymbolAddress((void**)&pV, g_V16);
    cudaGetSymbolAddress((void**)&pX, g_X16);
    cudaGetSymbolAddress((void**)&pIn, g_in16);
    cudaGetSymbolAddress((void**)&pWp, g_Wp);
    cudaGetSymbolAddress((void**)&pVp, g_Vp);
    cudaGetSymbolAddress((void**)&pInv, g_inv);

    const size_t M8 = 8u * 1024u * 1024u;
    const size_t W5 = 512u * 1024u;

    cudaFuncSetAttribute(gemm_fp16, cudaFuncAttributeMaxDynamicSharedMemorySize, GEMM_SMEM);
    cudaFuncSetAttribute(attn_fp16, cudaFuncAttributeMaxDynamicSharedMemorySize, ATT_SMEM);

    // conversions
    cvt_in4<<<dim3(4096, 4), 256>>>(query, key, value, adj, pIn);
    cvt_wp<<<dim3(512, 4), 256>>>(Wq, Wk, Wv, Wo, pWp);

    // fused QKV projection (fp16 out)
    {
        GemmArgs a{};
        a.A[0] = pIn; a.A[1] = pIn + M8; a.A[2] = pIn + 2 * M8;
        a.B[0] = pWp; a.B[1] = pWp + W5; a.B[2] = pWp + 2 * W5;
        a.bias[0] = bq; a.bias[1] = bk; a.bias[2] = bv;
        a.C[0] = pQ; a.C[1] = pK; a.C[2] = pV;
        a.inv = pInv; a.Xin = pX;
        a.sA = a.sB = a.sC = 0;
        a.nsel = 3; a.cmode = 0;
        gemm_fp16<<<dim3(8, 64, 3), 128, GEMM_SMEM>>>(a);
    }

    // k-paired V for B-side consumption
    pairV<<<2048, 256>>>(pV, pVp);

    rowsum_inv<<<1024, 256>>>(adj, pInv);

    // attention half -> X16
    attn_fp16<<<dim3(16, 16, 8), 128, ATT_SMEM>>>(pQ, pK, pVp, mask, pX);

    // adjacency half: X16 = fp16(0.5*diag(inv)*(adj@V) + X16), batched
    {
        GemmArgs a{};
        a.A[0] = pIn + 3 * M8;   // adj fp16
        a.B[0] = pVp;
        a.bias[0] = bq; // unused
        a.C[0] = pX;
        a.inv = pInv; a.Xin = pX;
        a.sA = 1024u * 1024u; a.sB = W5; a.sC = 1024u * 1024u;
        a.nsel = 1; a.cmode = 1;
        gemm_fp16<<<dim3(8, 8, 8), 128, GEMM_SMEM>>>(a);
    }

    // output projection (fp32 out + bias)
    {
        GemmArgs a{};
        a.A[0] = pX;
        a.B[0] = pWp + 3 * W5;
        a.bias[0] = bo;
        a.C[0] = out;
        a.inv = pInv; a.Xin = pX;
        a.sA = a.sB = a.sC = 0;
        a.nsel = 1; a.cmode = 2;
        gemm_fp16<<<dim3(8, 64, 1), 128, GEMM_SMEM>>>(a);
    }
}

// round 10
// speedup vs baseline: 1.7103x; 1.1534x over previous
#include <cuda_runtime.h>
#include <cuda_fp16.h>
#include <cstdint>

// ============================================================================
// Problem: B=8, N=1024, D=1024, H=16, dk=64
// out = (0.5*softmax(QK^T/8, key-masked) + 0.5*row_norm(adj)) @ V  -> @Wo + bo
// mma.sync m16n8k16 fp16 everywhere, fp32 accumulate.
// R10: all fragments loaded via ldmatrix. B-operands stored n-major ([n][k]):
// weights transposed at load, V transposed once per launch, K already [key][d].
// ============================================================================

__device__ __half g_Q16[8u * 1024u * 1024u];
__device__ __half g_K16[8u * 1024u * 1024u];
__device__ __half g_V16[8u * 1024u * 1024u];
__device__ __half g_X16[8u * 1024u * 1024u];
__device__ __half g_in16[4u * 8u * 1024u * 1024u];  // q|k|v|adj fp16 row-major
__device__ __half g_WT[4u * 1024u * 1024u];         // W^T fp16 (n-major): q|k|v|o
__device__ __half g_VT[8u * 1024u * 1024u];         // V^T fp16 per batch [d_model][tok]
__device__ float  g_inv[8u * 1024u];

// ---------------------------------------------------------------------------
__device__ __forceinline__ uint32_t smem_to_u32(const void* p) {
    uint32_t a;
    asm("{ .reg .u64 t; cvta.to.shared.u64 t, %1; cvt.u32.u64 %0, t; }" : "=r"(a) : "l"(p));
    return a;
}
__device__ __forceinline__ void cp_async16(uint32_t s, const void* g) {
    asm volatile("cp.async.cg.shared.global [%0], [%1], 16;" :: "r"(s), "l"(g));
}
#define CP_COMMIT() asm volatile("cp.async.commit_group;" ::: "memory")
#define CP_WAIT(n)  asm volatile("cp.async.wait_group %0;" :: "n"(n) : "memory")

__device__ __forceinline__ void mma_fp16(float* c, const uint32_t* a, const uint32_t* b) {
    asm volatile(
        "mma.sync.aligned.m16n8k16.row.col.f32.f16.f16.f32 "
        "{%0,%1,%2,%3}, {%4,%5,%6,%7}, {%8,%9}, {%0,%1,%2,%3};"
        : "+f"(c[0]), "+f"(c[1]), "+f"(c[2]), "+f"(c[3])
        : "r"(a[0]), "r"(a[1]), "r"(a[2]), "r"(a[3]), "r"(b[0]), "r"(b[1]));
}
__device__ __forceinline__ void ldsm_x4(uint32_t* r, uint32_t addr) {
    asm volatile("ldmatrix.sync.aligned.m8n8.x4.shared.b16 {%0,%1,%2,%3}, [%4];"
        : "=r"(r[0]), "=r"(r[1]), "=r"(r[2]), "=r"(r[3]) : "r"(addr));
}
__device__ __forceinline__ void ldsm_x2(uint32_t* r, uint32_t addr) {
    asm volatile("ldmatrix.sync.aligned.m8n8.x2.shared.b16 {%0,%1}, [%2];"
        : "=r"(r[0]), "=r"(r[1]) : "r"(addr));
}
__device__ __forceinline__ uint32_t pack_h2(float lo, float hi) {
    __half2 h = __floats2half2_rn(lo, hi);
    return *(uint32_t*)&h;
}

// ---------------------------------------------------------------------------
// inputs (q,k,v,adj) fp32 -> fp16 row-major; grid (4096, 4)
// ---------------------------------------------------------------------------
__global__ __launch_bounds__(256) void cvt_in4(
    const float* __restrict__ q, const float* __restrict__ k,
    const float* __restrict__ v, const float* __restrict__ adj,
    __half* __restrict__ out)
{
    const float* src = (blockIdx.y == 0) ? q : (blockIdx.y == 1) ? k
                     : (blockIdx.y == 2) ? v : adj;
    size_t idx = (size_t)blockIdx.x * 256 + threadIdx.x;
    float4 a = ((const float4*)src)[idx * 2];
    float4 b = ((const float4*)src)[idx * 2 + 1];
    uint4 o;
    o.x = pack_h2(a.x, a.y); o.y = pack_h2(a.z, a.w);
    o.z = pack_h2(b.x, b.y); o.w = pack_h2(b.z, b.w);
    ((uint4*)(out + (size_t)blockIdx.y * 8u * 1024u * 1024u))[idx] = o;
}

// ---------------------------------------------------------------------------
// weights fp32 [k][n] -> fp16 W^T [n][k]; 64x64 tiles, grid (16,16,4)
// ---------------------------------------------------------------------------
__global__ __launch_bounds__(256) void transposeW(
    const float* __restrict__ w0, const float* __restrict__ w1,
    const float* __restrict__ w2, const float* __restrict__ w3,
    __half* __restrict__ out)
{
    __shared__ __half S[64][80];
    const float* W = (blockIdx.z == 0) ? w0 : (blockIdx.z == 1) ? w1
                   : (blockIdx.z == 2) ? w2 : w3;
    const int k0 = blockIdx.y * 64, n0 = blockIdx.x * 64;
    const int tid = threadIdx.x;
#pragma unroll
    for (int i = 0; i < 4; i++) {
        int chunk = tid + i * 256;            // 1024 float4 chunks
        int r = chunk >> 4, c = (chunk & 15) * 4;
        float4 v = *(const float4*)(W + (size_t)(k0 + r) * 1024 + n0 + c);
        S[r][c + 0] = __float2half(v.x);
        S[r][c + 1] = __float2half(v.y);
        S[r][c + 2] = __float2half(v.z);
        S[r][c + 3] = __float2half(v.w);
    }
    __syncthreads();
    __half* OT = out + (size_t)blockIdx.z * 1024u * 1024u;
#pragma unroll
    for (int i = 0; i < 2; i++) {
        int chunk = tid + i * 256;            // 512 uint4 out chunks
        int nn = chunk >> 3, kc = (chunk & 7) * 8;
        __half tmp[8];
#pragma unroll
        for (int q = 0; q < 8; q++) tmp[q] = S[kc + q][nn];
        *(uint4*)(OT + (size_t)(n0 + nn) * 1024 + k0 + kc) = *(uint4*)tmp;
    }
}

// ---------------------------------------------------------------------------
// V fp16 [b][tok][d_model] -> V^T [b][d_model][tok]; 64x64 tiles, grid (16,16,8)
// ---------------------------------------------------------------------------
__global__ __launch_bounds__(256) void transposeV(
    const __half* __restrict__ V, __half* __restrict__ VT)
{
    __shared__ __half S[64][80];
    const int b = blockIdx.z;
    const int t0 = blockIdx.x * 64, d0 = blockIdx.y * 64;
    const int tid = threadIdx.x;
#pragma unroll
    for (int i = 0; i < 2; i++) {
        int chunk = tid + i * 256;            // 512 uint4 in chunks
        int r = chunk >> 3, c = (chunk & 7) * 8;
        *(uint4*)&S[r][c] =
            *(const uint4*)(V + ((size_t)b * 1024 + t0 + r) * 1024 + d0 + c);
    }
    __syncthreads();
#pragma unroll
    for (int i = 0; i < 2; i++) {
        int chunk = tid + i * 256;
        int dd = chunk >> 3, tc = (chunk & 7) * 8;
        __half tmp[8];
#pragma unroll
        for (int q = 0; q < 8; q++) tmp[q] = S[tc + q][dd];
        *(uint4*)(VT + ((size_t)b * 1024 + d0 + dd) * 1024 + t0 + tc) = *(uint4*)tmp;
    }
}

// ---------------------------------------------------------------------------
// adjacency row-sum -> 1/(sum+eps); one warp per row (fp32 source)
// ---------------------------------------------------------------------------
__global__ __launch_bounds__(256) void rowsum_inv(
    const float* __restrict__ adj, float* __restrict__ inv)
{
    const int row = blockIdx.x * 8 + (threadIdx.x >> 5);
    const int lane = threadIdx.x & 31;
    const float4* a = (const float4*)(adj + (size_t)row * 1024);
    float s = 0.f;
#pragma unroll
    for (int i = 0; i < 8; i++) {
        float4 v = a[lane + i * 32];
        s += (v.x + v.y) + (v.z + v.w);
    }
#pragma unroll
    for (int o = 16; o > 0; o >>= 1) s += __shfl_xor_sync(0xffffffffu, s, o);
    if (lane == 0) inv[row] = 1.0f / (s + 1e-6f);
}

// ---------------------------------------------------------------------------
// fp16 GEMM, ldmatrix fragments. C[M,1024] = A[M,1024] @ B^T'[1024n][1024k]
// A fp16 row-major, B fp16 n-major. 128 threads, 4 warps (2x2), block 128x128,
// warp 64x64, k-tile 32, 4-stage cp.async, 2 CTAs/SM.
// cmode 0: C(fp16)=D+bias; 1: C(fp16)=0.5*inv*D+Xin; 2: C(fp32)=D+bias
// ---------------------------------------------------------------------------
#define PA 20                       // smem pitch (words) for both tiles
#define TSTG (128 * PA)             // 2560 words per tile
#define STG_STRIDE (2 * TSTG)       // 5120 words per stage
#define NSTG 4
#define GEMM_SMEM (STG_STRIDE * NSTG * 4)   // 81920 bytes

struct GemmArgs {
    const __half* A[3];
    const __half* B[3];
    const float* bias[3];
    void* C[3];
    const float* inv;
    const __half* Xin;
    size_t sA, sB, sC;
    int nsel;
    int cmode;
};

__global__ __launch_bounds__(128, 2) void gemm_fp16(GemmArgs args)
{
    extern __shared__ uint32_t smw[];
    const uint32_t base_u = smem_to_u32(smw);

    const int tid = threadIdx.x;
    const int wid = tid >> 5, lane = tid & 31;
    const int wm = wid >> 1, wn = wid & 1;
    const int g = lane >> 2, t = lane & 3;

    const int sel = (args.nsel > 1) ? blockIdx.z : 0;
    const int z   = (args.nsel > 1) ? 0 : blockIdx.z;

    const __half* Ab = args.A[sel] + (size_t)z * args.sA + (size_t)(blockIdx.y * 128) * 1024;
    const __half* Bb = args.B[sel] + (size_t)z * args.sB + (size_t)(blockIdx.x * 128) * 1024;

    const int ld_r = tid >> 2, ld_c = (tid & 3) * 4;   // rows +i*32, 4-word col

    // ldmatrix lane offsets (words)
    const uint32_t aOff = (uint32_t)((wm * 64 + (lane & 15)) * PA + ((lane & 16) ? 4 : 0));
    const uint32_t bOff = (uint32_t)((wn * 64 + (lane & 7)) * PA + ((lane & 8) ? 4 : 0));

    float c[4][8][4];
#pragma unroll
    for (int i = 0; i < 4; i++)
#pragma unroll
        for (int j = 0; j < 8; j++)
#pragma unroll
            for (int q = 0; q < 4; q++) c[i][j][q] = 0.f;

    auto load_stage = [&](int kt, int stg) {
        const uint32_t as_u = base_u + (uint32_t)(stg * STG_STRIDE) * 4;
        const uint32_t bs_u = as_u + (uint32_t)TSTG * 4;
#pragma unroll
        for (int i = 0; i < 4; i++) {
            int r = ld_r + i * 32;
            cp_async16(as_u + (uint32_t)(r * PA + ld_c) * 4,
                       Ab + (size_t)r * 1024 + kt * 32 + ld_c * 2);
            cp_async16(bs_u + (uint32_t)(r * PA + ld_c) * 4,
                       Bb + (size_t)r * 1024 + kt * 32 + ld_c * 2);
        }
        CP_COMMIT();
    };

    load_stage(0, 0);
    load_stage(1, 1);
    load_stage(2, 2);

    int stg = 0;
    for (int kt = 0; kt < 32; kt++) {
        if (kt + 3 < 32) { load_stage(kt + 3, (kt + 3) & 3); CP_WAIT(3); }
        else { CP_WAIT(0); }
        __syncthreads();

        const uint32_t as_u = base_u + (uint32_t)(stg * STG_STRIDE) * 4;
        const uint32_t bs_u = as_u + (uint32_t)TSTG * 4;
#pragma unroll
        for (int ks = 0; ks < 2; ks++) {
            uint32_t af[4][4];
#pragma unroll
            for (int i = 0; i < 4; i++)
                ldsm_x4(af[i], as_u + (aOff + i * 16 * PA + ks * 8) * 4);
            uint32_t bf[8][2];
#pragma unroll
            for (int j = 0; j < 8; j++)
                ldsm_x2(bf[j], bs_u + (bOff + j * 8 * PA + ks * 8) * 4);
#pragma unroll
            for (int i = 0; i < 4; i++)
#pragma unroll
                for (int j = 0; j < 8; j++)
                    mma_fp16(c[i][j], af[i], bf[j]);
        }
        __syncthreads();
        stg = (stg + 1) & 3;
    }

    // ---- epilogue ----
    const int colW = blockIdx.x * 128 + wn * 64;
    const float* bias = args.bias[sel];
    const int cmode = args.cmode;

#pragma unroll
    for (int i = 0; i < 4; i++) {
        const int row0 = blockIdx.y * 128 + wm * 64 + i * 16 + g;
        const int row1 = row0 + 8;
        if (cmode == 0) {
            __half2* C16 = (__half2*)args.C[sel];
#pragma unroll
            for (int j = 0; j < 8; j++) {
                const int col = colW + j * 8 + 2 * t;
                const float b0 = bias[col], b1 = bias[col + 1];
                C16[(size_t)row0 * 512 + (col >> 1)] =
                    __floats2half2_rn(c[i][j][0] + b0, c[i][j][1] + b1);
                C16[(size_t)row1 * 512 + (col >> 1)] =
                    __floats2half2_rn(c[i][j][2] + b0, c[i][j][3] + b1);
            }
        } else if (cmode == 1) {
            __half2* C16 = (__half2*)args.C[0] + (size_t)z * (args.sC >> 1);
            const __half2* X16 = (const __half2*)args.Xin + (size_t)z * (args.sC >> 1);
            const float s0 = 0.5f * args.inv[z * 1024 + row0];
            const float s1 = 0.5f * args.inv[z * 1024 + row1];
#pragma unroll
            for (int j = 0; j < 8; j++) {
                const int col = colW + j * 8 + 2 * t;
                float2 x0 = __half22float2(X16[(size_t)row0 * 512 + (col >> 1)]);
                float2 x1 = __half22float2(X16[(size_t)row1 * 512 + (col >> 1)]);
                C16[(size_t)row0 * 512 + (col >> 1)] =
                    __floats2half2_rn(s0 * c[i][j][0] + x0.x, s0 * c[i][j][1] + x0.y);
                C16[(size_t)row1 * 512 + (col >> 1)] =
                    __floats2half2_rn(s1 * c[i][j][2] + x1.x, s1 * c[i][j][3] + x1.y);
            }
        } else {
            float* Cf = (float*)args.C[0];
#pragma unroll
            for (int j = 0; j < 8; j++) {
                const int col = colW + j * 8 + 2 * t;
                const float b0 = bias[col], b1 = bias[col + 1];
                *(float2*)(Cf + (size_t)row0 * 1024 + col) =
                    make_float2(c[i][j][0] + b0, c[i][j][1] + b1);
                *(float2*)(Cf + (size_t)row1 * 1024 + col) =
                    make_float2(c[i][j][2] + b0, c[i][j][3] + b1);
            }
        }
    }
}

// ---------------------------------------------------------------------------
// fp16 flash attention half, ldmatrix fragments:
// X16[b,q,h*64+d] = fp16( 0.5 * softmax(QK^T/8, key-masked) @ V )
// Qs/Ks/Ps: [64][64] fp16 rows pitch 36 words; Vs = V^T tile [64 d][64 key].
// ---------------------------------------------------------------------------
#define QP16 36
#define ATT_SMEM (4 * 64 * QP16 * 4)   // 36864 bytes

__global__ __launch_bounds__(128) void attn_fp16(
    const __half* __restrict__ Q, const __half* __restrict__ K,
    const __half* __restrict__ VT, const int* __restrict__ mask,
    __half* __restrict__ X)
{
    extern __shared__ uint32_t smu[];
    uint32_t* Qs = smu;                    // [64][QP16]
    uint32_t* Ks = smu + 64 * QP16;
    uint32_t* Ps = smu + 128 * QP16;
    uint32_t* Vs = smu + 192 * QP16;       // [64 d][QP16]
    __shared__ int msk[64];

    const uint32_t base_u = smem_to_u32(smu);
    const uint32_t Qs_u = base_u;
    const uint32_t Ks_u = base_u + 64 * QP16 * 4;
    const uint32_t Ps_u = base_u + 128 * QP16 * 4;
    const uint32_t Vs_u = base_u + 192 * QP16 * 4;

    const int tid = threadIdx.x;
    const int wid = tid >> 5, lane = tid & 31;
    const int g = lane >> 2, t = lane & 3;
    const int b = blockIdx.z, h = blockIdx.y;
    const int q0 = blockIdx.x * 64;

    const __half* Qb = Q + ((size_t)b * 1024 + q0) * 1024 + h * 64;
    const __half* Kb = K + (size_t)b * 1024 * 1024 + h * 64;
    const __half* VTb = VT + ((size_t)b * 1024 + h * 64) * 1024;
    const int* mb = mask + b * 1024;

    // ldmatrix lane offsets (words)
    const uint32_t aOff = (uint32_t)((wid * 16 + (lane & 15)) * QP16 + ((lane & 16) ? 4 : 0));
    const uint32_t bOff = (uint32_t)((lane & 7) * QP16 + ((lane & 8) ? 4 : 0));

    // Q tile: 64 rows x 32 words
    for (int idx = tid; idx < 512; idx += 128) {
        int r = idx >> 3, c = (idx & 7) * 4;
        *(uint4*)(Qs + r * QP16 + c) = *(const uint4*)(Qb + (size_t)r * 1024 + c * 2);
    }

    float m0 = -1e30f, m1 = -1e30f, l0 = 0.f, l1 = 0.f;
    float o[8][4];
#pragma unroll
    for (int j = 0; j < 8; j++)
#pragma unroll
        for (int q = 0; q < 4; q++) o[j][q] = 0.f;

    const int rowA = wid * 16 + g;

    for (int kb = 0; kb < 1024; kb += 64) {
        __syncthreads();
        for (int idx = tid; idx < 512; idx += 128) {
            int r = idx >> 3, c = (idx & 7) * 4;
            *(uint4*)(Ks + r * QP16 + c) =
                *(const uint4*)(Kb + (size_t)(kb + r) * 1024 + c * 2);
            *(uint4*)(Vs + r * QP16 + c) =
                *(const uint4*)(VTb + (size_t)r * 1024 + kb + c * 2);
        }
        if (tid < 64) msk[tid] = mb[kb + tid];
        __syncthreads();

        // ---- S = Q K^T : 4 ks-steps over d ----
        float s[8][4];
#pragma unroll
        for (int j = 0; j < 8; j++)
#pragma unroll
            for (int q = 0; q < 4; q++) s[j][q] = 0.f;

#pragma unroll
        for (int ks = 0; ks < 4; ks++) {
            uint32_t a[4];
            ldsm_x4(a, Qs_u + (aOff + ks * 8) * 4);
#pragma unroll
            for (int j = 0; j < 8; j++) {
                uint32_t bb[2];
                ldsm_x2(bb, Ks_u + (bOff + j * 8 * QP16 + ks * 8) * 4);
                mma_fp16(s[j], a, bb);
            }
        }

        // ---- scale + mask; online softmax ----
        float tm0 = -1e30f, tm1 = -1e30f;
#pragma unroll
        for (int j = 0; j < 8; j++) {
            const bool d0 = (msk[j * 8 + 2 * t] == 0);
            const bool d1 = (msk[j * 8 + 2 * t + 1] == 0);
            s[j][0] = d0 ? -1e12f : s[j][0] * 0.125f;
            s[j][1] = d1 ? -1e12f : s[j][1] * 0.125f;
            s[j][2] = d0 ? -1e12f : s[j][2] * 0.125f;
            s[j][3] = d1 ? -1e12f : s[j][3] * 0.125f;
            tm0 = fmaxf(tm0, fmaxf(s[j][0], s[j][1]));
            tm1 = fmaxf(tm1, fmaxf(s[j][2], s[j][3]));
        }
        tm0 = fmaxf(tm0, __shfl_xor_sync(0xffffffffu, tm0, 1));
        tm0 = fmaxf(tm0, __shfl_xor_sync(0xffffffffu, tm0, 2));
        tm1 = fmaxf(tm1, __shfl_xor_sync(0xffffffffu, tm1, 1));
        tm1 = fmaxf(tm1, __shfl_xor_sync(0xffffffffu, tm1, 2));

        const float mn0 = fmaxf(m0, tm0), mn1 = fmaxf(m1, tm1);
        const float al0 = __expf(m0 - mn0), al1 = __expf(m1 - mn1);
        m0 = mn0; m1 = mn1;

        float ts0 = 0.f, ts1 = 0.f;
#pragma unroll
        for (int j = 0; j < 8; j++) {
            s[j][0] = __expf(s[j][0] - mn0);
            s[j][1] = __expf(s[j][1] - mn0);
            s[j][2] = __expf(s[j][2] - mn1);
            s[j][3] = __expf(s[j][3] - mn1);
            ts0 += s[j][0] + s[j][1];
            ts1 += s[j][2] + s[j][3];
        }
        ts0 += __shfl_xor_sync(0xffffffffu, ts0, 1);
        ts0 += __shfl_xor_sync(0xffffffffu, ts0, 2);
        ts1 += __shfl_xor_sync(0xffffffffu, ts1, 1);
        ts1 += __shfl_xor_sync(0xffffffffu, ts1, 2);
        l0 = l0 * al0 + ts0;
        l1 = l1 * al1 + ts1;

#pragma unroll
        for (int j = 0; j < 8; j++) {
            o[j][0] *= al0; o[j][1] *= al0;
            o[j][2] *= al1; o[j][3] *= al1;
        }

        // ---- stage P as row-major fp16 [q][key] (words) ----
#pragma unroll
        for (int j = 0; j < 8; j++) {
            Ps[rowA * QP16 + j * 4 + t]       = pack_h2(s[j][0], s[j][1]);
            Ps[(rowA + 8) * QP16 + j * 4 + t] = pack_h2(s[j][2], s[j][3]);
        }
        __syncwarp();

        // ---- O += P V : 4 ks-steps over keys ----
#pragma unroll
        for (int ks = 0; ks < 4; ks++) {
            uint32_t a[4];
            ldsm_x4(a, Ps_u + (aOff + ks * 8) * 4);
#pragma unroll
            for (int j = 0; j < 8; j++) {
                uint32_t bb[2];
                ldsm_x2(bb, Vs_u + (bOff + j * 8 * QP16 + ks * 8) * 4);
                mma_fp16(o[j], a, bb);
            }
        }
    }

    // ---- epilogue: X16 = fp16(0.5 * O / l) ----
    const float sc0 = 0.5f / l0, sc1 = 0.5f / l1;
    __half2* Xr0 = (__half2*)X + ((size_t)b * 1024 + q0 + rowA) * 512 + h * 32;
    __half2* Xr1 = Xr0 + (size_t)8 * 512;
#pragma unroll
    for (int j = 0; j < 8; j++) {
        Xr0[j * 4 + t] = __floats2half2_rn(o[j][0] * sc0, o[j][1] * sc0);
        Xr1[j * 4 + t] = __floats2half2_rn(o[j][2] * sc1, o[j][3] * sc1);
    }
}

// ---------------------------------------------------------------------------
extern "C" void kernel_launch(void* const* d_in, const int* in_sizes, int n_in,
                              void* d_out, int out_size)
{
    const float* query = (const float*)d_in[0];
    const float* key   = (const float*)d_in[1];
    const float* value = (const float*)d_in[2];
    const float* adj   = (const float*)d_in[3];
    const int*   mask  = (const int*)d_in[5];
    const float* Wq = (const float*)d_in[6];
    const float* bq = (const float*)d_in[7];
    const float* Wk = (const float*)d_in[8];
    const float* bk = (const float*)d_in[9];
    const float* Wv = (const float*)d_in[10];
    const float* bv = (const float*)d_in[11];
    const float* Wo = (const float*)d_in[12];
    const float* bo = (const float*)d_in[13];
    float* out = (float*)d_out;

    __half *pQ, *pK, *pV, *pX, *pIn, *pWT, *pVT;
    float *pInv;
    cudaGetSymbolAddress((void**)&pQ, g_Q16);
    cudaGetSymbolAddress((void**)&pK, g_K16);
    cudaGetSymbolAddress((void**)&pV, g_V16);
    cudaGetSymbolAddress((void**)&pX, g_X16);
    cudaGetSymbolAddress((void**)&pIn, g_in16);
    cudaGetSymbolAddress((void**)&pWT, g_WT);
    cudaGetSymbolAddress((void**)&pVT, g_VT);
    cudaGetSymbolAddress((void**)&pInv, g_inv);

    const size_t M8 = 8u * 1024u * 1024u;
    const size_t M1 = 1024u * 1024u;

    cudaFuncSetAttribute(gemm_fp16, cudaFuncAttributeMaxDynamicSharedMemorySize, GEMM_SMEM);
    cudaFuncSetAttribute(attn_fp16, cudaFuncAttributeMaxDynamicSharedMemorySize, ATT_SMEM);

    // conversions
    cvt_in4<<<dim3(4096, 4), 256>>>(query, key, value, adj, pIn);
    transposeW<<<dim3(16, 16, 4), 256>>>(Wq, Wk, Wv, Wo, pWT);

    // fused QKV projection (fp16 out)
    {
        GemmArgs a{};
        a.A[0] = pIn; a.A[1] = pIn + M8; a.A[2] = pIn + 2 * M8;
        a.B[0] = pWT; a.B[1] = pWT + M1; a.B[2] = pWT + 2 * M1;
        a.bias[0] = bq; a.bias[1] = bk; a.bias[2] = bv;
        a.C[0] = pQ; a.C[1] = pK; a.C[2] = pV;
        a.inv = pInv; a.Xin = pX;
        a.sA = a.sB = a.sC = 0;
        a.nsel = 3; a.cmode = 0;
        gemm_fp16<<<dim3(8, 64, 3), 128, GEMM_SMEM>>>(a);
    }

    // V^T for B-side consumption (adj-gemm + attention PV)
    transposeV<<<dim3(16, 16, 8), 256>>>(pV, pVT);

    rowsum_inv<<<1024, 256>>>(adj, pInv);

    // attention half -> X16
    attn_fp16<<<dim3(16, 16, 8), 128, ATT_SMEM>>>(pQ, pK, pVT, mask, pX);

    // adjacency half: X16 = fp16(0.5*diag(inv)*(adj@V) + X16), batched
    {
        GemmArgs a{};
        a.A[0] = pIn + 3 * M8;   // adj fp16 row-major
        a.B[0] = pVT;            // V^T (n-major)
        a.bias[0] = bq;          // unused
        a.C[0] = pX;
        a.inv = pInv; a.Xin = pX;
        a.sA = M1; a.sB = M1; a.sC = M1;
        a.nsel = 1; a.cmode = 1;
        gemm_fp16<<<dim3(8, 8, 8), 128, GEMM_SMEM>>>(a);
    }

    // output projection (fp32 out + bias)
    {
        GemmArgs a{};
        a.A[0] = pX;
        a.B[0] = pWT + 3 * M1;
        a.bias[0] = bo;
        a.C[0] = out;
        a.inv = pInv; a.Xin = pX;
        a.sA = a.sB = a.sC = 0;
        a.nsel = 1; a.cmode = 2;
        gemm_fp16<<<dim3(8, 64, 1), 128, GEMM_SMEM>>>(a);
    }
}

// round 11
// speedup vs baseline: 1.9993x; 1.1690x over previous
#include <cuda_runtime.h>
#include <cuda_fp16.h>
#include <cstdint>

// ============================================================================
// Problem: B=8, N=1024, D=1024, H=16, dk=64
// out = (0.5*softmax(QK^T/8, key-masked) + 0.5*row_norm(adj)) @ V  -> @Wo + bo
// mma.sync m16n8k16 fp16, fp32 accumulate. All fragments via ldmatrix;
// B-operands consumed from ROW-MAJOR tiles via ldmatrix.trans (no transpose
// kernels). GEMM k-tile 64, 3-stage cp.async, 2 CTAs/SM.
// ============================================================================

__device__ __half g_Q16[8u * 1024u * 1024u];
__device__ __half g_K16[8u * 1024u * 1024u];
__device__ __half g_V16[8u * 1024u * 1024u];
__device__ __half g_X16[8u * 1024u * 1024u];
__device__ __half g_in16[4u * 8u * 1024u * 1024u];  // q|k|v|adj fp16 row-major
__device__ __half g_W16[4u * 1024u * 1024u];        // Wq|Wk|Wv|Wo fp16 row-major
__device__ float  g_inv[8u * 1024u];

// ---------------------------------------------------------------------------
__device__ __forceinline__ uint32_t smem_to_u32(const void* p) {
    uint32_t a;
    asm("{ .reg .u64 t; cvta.to.shared.u64 t, %1; cvt.u32.u64 %0, t; }" : "=r"(a) : "l"(p));
    return a;
}
__device__ __forceinline__ void cp_async16(uint32_t s, const void* g) {
    asm volatile("cp.async.cg.shared.global [%0], [%1], 16;" :: "r"(s), "l"(g));
}
#define CP_COMMIT() asm volatile("cp.async.commit_group;" ::: "memory")
#define CP_WAIT(n)  asm volatile("cp.async.wait_group %0;" :: "n"(n) : "memory")

__device__ __forceinline__ void mma_fp16(float* c, const uint32_t* a, const uint32_t* b) {
    asm volatile(
        "mma.sync.aligned.m16n8k16.row.col.f32.f16.f16.f32 "
        "{%0,%1,%2,%3}, {%4,%5,%6,%7}, {%8,%9}, {%0,%1,%2,%3};"
        : "+f"(c[0]), "+f"(c[1]), "+f"(c[2]), "+f"(c[3])
        : "r"(a[0]), "r"(a[1]), "r"(a[2]), "r"(a[3]), "r"(b[0]), "r"(b[1]));
}
__device__ __forceinline__ void ldsm_x4(uint32_t* r, uint32_t addr) {
    asm volatile("ldmatrix.sync.aligned.m8n8.x4.shared.b16 {%0,%1,%2,%3}, [%4];"
        : "=r"(r[0]), "=r"(r[1]), "=r"(r[2]), "=r"(r[3]) : "r"(addr));
}
__device__ __forceinline__ void ldsm_x4t(uint32_t* r, uint32_t addr) {
    asm volatile("ldmatrix.sync.aligned.m8n8.x4.trans.shared.b16 {%0,%1,%2,%3}, [%4];"
        : "=r"(r[0]), "=r"(r[1]), "=r"(r[2]), "=r"(r[3]) : "r"(addr));
}
__device__ __forceinline__ uint32_t pack_h2(float lo, float hi) {
    __half2 h = __floats2half2_rn(lo, hi);
    return *(uint32_t*)&h;
}

// ---------------------------------------------------------------------------
// inputs (q,k,v,adj) fp32 -> fp16 row-major; grid (4096, 4)
// ---------------------------------------------------------------------------
__global__ __launch_bounds__(256) void cvt_in4(
    const float* __restrict__ q, const float* __restrict__ k,
    const float* __restrict__ v, const float* __restrict__ adj,
    __half* __restrict__ out)
{
    const float* src = (blockIdx.y == 0) ? q : (blockIdx.y == 1) ? k
                     : (blockIdx.y == 2) ? v : adj;
    size_t idx = (size_t)blockIdx.x * 256 + threadIdx.x;
    float4 a = ((const float4*)src)[idx * 2];
    float4 b = ((const float4*)src)[idx * 2 + 1];
    uint4 o;
    o.x = pack_h2(a.x, a.y); o.y = pack_h2(a.z, a.w);
    o.z = pack_h2(b.x, b.y); o.w = pack_h2(b.z, b.w);
    ((uint4*)(out + (size_t)blockIdx.y * 8u * 1024u * 1024u))[idx] = o;
}

// weights fp32 -> fp16 row-major (no transpose); grid (512, 4)
__global__ __launch_bounds__(256) void cvt_w4(
    const float* __restrict__ w0, const float* __restrict__ w1,
    const float* __restrict__ w2, const float* __restrict__ w3,
    __half* __restrict__ out)
{
    const float* src = (blockIdx.y == 0) ? w0 : (blockIdx.y == 1) ? w1
                     : (blockIdx.y == 2) ? w2 : w3;
    size_t idx = (size_t)blockIdx.x * 256 + threadIdx.x;
    float4 a = ((const float4*)src)[idx * 2];
    float4 b = ((const float4*)src)[idx * 2 + 1];
    uint4 o;
    o.x = pack_h2(a.x, a.y); o.y = pack_h2(a.z, a.w);
    o.z = pack_h2(b.x, b.y); o.w = pack_h2(b.z, b.w);
    ((uint4*)(out + (size_t)blockIdx.y * 1024u * 1024u))[idx] = o;
}

// ---------------------------------------------------------------------------
// adjacency row-sum -> 1/(sum+eps); one warp per row (fp32 source)
// ---------------------------------------------------------------------------
__global__ __launch_bounds__(256) void rowsum_inv(
    const float* __restrict__ adj, float* __restrict__ inv)
{
    const int row = blockIdx.x * 8 + (threadIdx.x >> 5);
    const int lane = threadIdx.x & 31;
    const float4* a = (const float4*)(adj + (size_t)row * 1024);
    float s = 0.f;
#pragma unroll
    for (int i = 0; i < 8; i++) {
        float4 v = a[lane + i * 32];
        s += (v.x + v.y) + (v.z + v.w);
    }
#pragma unroll
    for (int o = 16; o > 0; o >>= 1) s += __shfl_xor_sync(0xffffffffu, s, o);
    if (lane == 0) inv[row] = 1.0f / (s + 1e-6f);
}

// ---------------------------------------------------------------------------
// fp16 GEMM: C[M,1024] = A[M,1024] @ B[1024,1024], BOTH row-major fp16.
// B-fragments via ldmatrix.x4.trans on row-major [k][n] tiles.
// 128 threads, 4 warps (2x2), block 128x128, warp 64x64, k-tile 64,
// 3-stage cp.async, 2 CTAs/SM.
// cmode 0: C(fp16)=D+bias; 1: C(fp16)=0.5*inv*D+Xin; 2: C(fp32)=D+bias
// ---------------------------------------------------------------------------
#define PA 36                        // A pitch (words), 128 rows x 32 data words
#define PB 68                        // B pitch (words), 64 rows x 64 data words
#define A_TILE (128 * PA)            // 4608 words
#define B_TILE (64 * PB)             // 4352 words
#define STG_STRIDE (A_TILE + B_TILE) // 8960 words
#define NSTG 3
#define GEMM_SMEM (STG_STRIDE * NSTG * 4)   // 107520 bytes

struct GemmArgs {
    const __half* A[3];
    const __half* B[3];
    const float* bias[3];
    void* C[3];
    const float* inv;
    const __half* Xin;
    size_t sA, sB, sC;
    int nsel;
    int cmode;
};

__global__ __launch_bounds__(128, 2) void gemm_fp16(GemmArgs args)
{
    extern __shared__ uint32_t smw[];
    const uint32_t base_u = smem_to_u32(smw);

    const int tid = threadIdx.x;
    const int wid = tid >> 5, lane = tid & 31;
    const int wm = wid >> 1, wn = wid & 1;
    const int g = lane >> 2, t = lane & 3;

    const int sel = (args.nsel > 1) ? blockIdx.z : 0;
    const int z   = (args.nsel > 1) ? 0 : blockIdx.z;

    const __half* Ab = args.A[sel] + (size_t)z * args.sA + (size_t)(blockIdx.y * 128) * 1024;
    const __half* Bb = args.B[sel] + (size_t)z * args.sB + blockIdx.x * 128;

    // ldmatrix lane offsets (words)
    const uint32_t aOff = (uint32_t)((wm * 64 + (lane & 15)) * PA + ((lane & 16) ? 4 : 0));
    const uint32_t bOff = (uint32_t)(((lane & 7) + ((lane & 8) ? 8 : 0)) * PB
                                     + wn * 32 + ((lane & 16) ? 4 : 0));

    float c[4][8][4];
#pragma unroll
    for (int i = 0; i < 4; i++)
#pragma unroll
        for (int j = 0; j < 8; j++)
#pragma unroll
            for (int q = 0; q < 4; q++) c[i][j][q] = 0.f;

    auto load_stage = [&](int kt, int stg) {
        const uint32_t as_u = base_u + (uint32_t)(stg * STG_STRIDE) * 4;
        const uint32_t bs_u = as_u + (uint32_t)A_TILE * 4;
        // A: 128 rows x 32 words -> 1024 f4 chunks, 8/thread
#pragma unroll
        for (int i = 0; i < 8; i++) {
            int ch = tid + i * 128;
            int r = ch >> 3, cw = (ch & 7) * 4;
            cp_async16(as_u + (uint32_t)(r * PA + cw) * 4,
                       Ab + (size_t)r * 1024 + kt * 64 + cw * 2);
        }
        // B: 64 rows x 64 words -> 1024 f4 chunks, 8/thread
#pragma unroll
        for (int i = 0; i < 8; i++) {
            int ch = tid + i * 128;
            int r = ch >> 4, cw = (ch & 15) * 4;
            cp_async16(bs_u + (uint32_t)(r * PB + cw) * 4,
                       Bb + (size_t)(kt * 64 + r) * 1024 + cw * 2);
        }
        CP_COMMIT();
    };

    load_stage(0, 0);
    load_stage(1, 1);

    int stg = 0;
    for (int kt = 0; kt < 16; kt++) {
        if (kt + 2 < 16) { load_stage(kt + 2, (kt + 2) % NSTG); CP_WAIT(2); }
        else if (kt + 1 < 16) { CP_WAIT(1); }
        else { CP_WAIT(0); }
        __syncthreads();

        const uint32_t as_u = base_u + (uint32_t)(stg * STG_STRIDE) * 4;
        const uint32_t bs_u = as_u + (uint32_t)A_TILE * 4;
#pragma unroll
        for (int ks = 0; ks < 4; ks++) {
            uint32_t af[4][4];
#pragma unroll
            for (int i = 0; i < 4; i++)
                ldsm_x4(af[i], as_u + (aOff + i * 16 * PA + ks * 8) * 4);
            uint32_t bf[8][2];
#pragma unroll
            for (int jj = 0; jj < 4; jj++) {
                uint32_t r4[4];
                ldsm_x4t(r4, bs_u + (bOff + ks * 16 * PB + jj * 8) * 4);
                bf[2 * jj][0] = r4[0]; bf[2 * jj][1] = r4[1];
                bf[2 * jj + 1][0] = r4[2]; bf[2 * jj + 1][1] = r4[3];
            }
#pragma unroll
            for (int i = 0; i < 4; i++)
#pragma unroll
                for (int j = 0; j < 8; j++)
                    mma_fp16(c[i][j], af[i], bf[j]);
        }
        __syncthreads();
        stg = (stg + 1) % NSTG;
    }

    // ---- epilogue ----
    const int colW = blockIdx.x * 128 + wn * 64;
    const float* bias = args.bias[sel];
    const int cmode = args.cmode;

#pragma unroll
    for (int i = 0; i < 4; i++) {
        const int row0 = blockIdx.y * 128 + wm * 64 + i * 16 + g;
        const int row1 = row0 + 8;
        if (cmode == 0) {
            __half2* C16 = (__half2*)args.C[sel];
#pragma unroll
            for (int j = 0; j < 8; j++) {
                const int col = colW + j * 8 + 2 * t;
                const float b0 = bias[col], b1 = bias[col + 1];
                C16[(size_t)row0 * 512 + (col >> 1)] =
                    __floats2half2_rn(c[i][j][0] + b0, c[i][j][1] + b1);
                C16[(size_t)row1 * 512 + (col >> 1)] =
                    __floats2half2_rn(c[i][j][2] + b0, c[i][j][3] + b1);
            }
        } else if (cmode == 1) {
            __half2* C16 = (__half2*)args.C[0] + (size_t)z * (args.sC >> 1);
            const __half2* X16 = (const __half2*)args.Xin + (size_t)z * (args.sC >> 1);
            const float s0 = 0.5f * args.inv[z * 1024 + row0];
            const float s1 = 0.5f * args.inv[z * 1024 + row1];
#pragma unroll
            for (int j = 0; j < 8; j++) {
                const int col = colW + j * 8 + 2 * t;
                float2 x0 = __half22float2(X16[(size_t)row0 * 512 + (col >> 1)]);
                float2 x1 = __half22float2(X16[(size_t)row1 * 512 + (col >> 1)]);
                C16[(size_t)row0 * 512 + (col >> 1)] =
                    __floats2half2_rn(s0 * c[i][j][0] + x0.x, s0 * c[i][j][1] + x0.y);
                C16[(size_t)row1 * 512 + (col >> 1)] =
                    __floats2half2_rn(s1 * c[i][j][2] + x1.x, s1 * c[i][j][3] + x1.y);
            }
        } else {
            float* Cf = (float*)args.C[0];
#pragma unroll
            for (int j = 0; j < 8; j++) {
                const int col = colW + j * 8 + 2 * t;
                const float b0 = bias[col], b1 = bias[col + 1];
                *(float2*)(Cf + (size_t)row0 * 1024 + col) =
                    make_float2(c[i][j][0] + b0, c[i][j][1] + b1);
                *(float2*)(Cf + (size_t)row1 * 1024 + col) =
                    make_float2(c[i][j][2] + b0, c[i][j][3] + b1);
            }
        }
    }
}

// ---------------------------------------------------------------------------
// fp16 flash attention half, all-ldmatrix, V consumed row-major (trans):
// X16[b,q,h*64+d] = fp16( 0.5 * softmax(QK^T/8, key-masked) @ V )
// Qs/Ks/Ps/Vs: [64][64] fp16, pitch 36 words. Vs = row-major V [key][d].
// ---------------------------------------------------------------------------
#define QP16 36
#define ATT_SMEM (4 * 64 * QP16 * 4)   // 36864 bytes

__global__ __launch_bounds__(128) void attn_fp16(
    const __half* __restrict__ Q, const __half* __restrict__ K,
    const __half* __restrict__ V, const int* __restrict__ mask,
    __half* __restrict__ X)
{
    extern __shared__ uint32_t smu[];
    uint32_t* Qs = smu;
    uint32_t* Ks = smu + 64 * QP16;
    uint32_t* Ps = smu + 128 * QP16;
    uint32_t* Vs = smu + 192 * QP16;
    __shared__ int msk[64];

    const uint32_t base_u = smem_to_u32(smu);
    const uint32_t Qs_u = base_u;
    const uint32_t Ks_u = base_u + 64 * QP16 * 4;
    const uint32_t Ps_u = base_u + 128 * QP16 * 4;
    const uint32_t Vs_u = base_u + 192 * QP16 * 4;

    const int tid = threadIdx.x;
    const int wid = tid >> 5, lane = tid & 31;
    const int g = lane >> 2, t = lane & 3;
    const int b = blockIdx.z, h = blockIdx.y;
    const int q0 = blockIdx.x * 64;

    const __half* Qb = Q + ((size_t)b * 1024 + q0) * 1024 + h * 64;
    const __half* Kb = K + (size_t)b * 1024 * 1024 + h * 64;
    const __half* Vb = V + (size_t)b * 1024 * 1024 + h * 64;
    const int* mb = mask + b * 1024;

    // ldmatrix lane offsets (words)
    const uint32_t aOff = (uint32_t)((wid * 16 + (lane & 15)) * QP16 + ((lane & 16) ? 4 : 0));
    // S (non-trans, Ks rows = keys): rows jj*16 + (lane&16?8:0) + (lane&7), col k-half by lane&8
    const uint32_t kOff = (uint32_t)(((lane & 7) + ((lane & 16) ? 8 : 0)) * QP16
                                     + ((lane & 8) ? 4 : 0));
    // PV (trans, Vs rows = keys = k): rows (lane&7) + (lane&8?8:0), col n-half by lane&16
    const uint32_t vOff = (uint32_t)(((lane & 7) + ((lane & 8) ? 8 : 0)) * QP16
                                     + ((lane & 16) ? 4 : 0));

    // Q tile: 64 rows x 32 words
    for (int idx = tid; idx < 512; idx += 128) {
        int r = idx >> 3, c = (idx & 7) * 4;
        *(uint4*)(Qs + r * QP16 + c) = *(const uint4*)(Qb + (size_t)r * 1024 + c * 2);
    }

    float m0 = -1e30f, m1 = -1e30f, l0 = 0.f, l1 = 0.f;
    float o[8][4];
#pragma unroll
    for (int j = 0; j < 8; j++)
#pragma unroll
        for (int q = 0; q < 4; q++) o[j][q] = 0.f;

    const int rowA = wid * 16 + g;

    for (int kb = 0; kb < 1024; kb += 64) {
        __syncthreads();
        for (int idx = tid; idx < 512; idx += 128) {
            int r = idx >> 3, c = (idx & 7) * 4;
            *(uint4*)(Ks + r * QP16 + c) =
                *(const uint4*)(Kb + (size_t)(kb + r) * 1024 + c * 2);
            *(uint4*)(Vs + r * QP16 + c) =
                *(const uint4*)(Vb + (size_t)(kb + r) * 1024 + c * 2);
        }
        if (tid < 64) msk[tid] = mb[kb + tid];
        __syncthreads();

        // ---- S = Q K^T : 4 ks-steps over d ----
        float s[8][4];
#pragma unroll
        for (int j = 0; j < 8; j++)
#pragma unroll
            for (int q = 0; q < 4; q++) s[j][q] = 0.f;

#pragma unroll
        for (int ks = 0; ks < 4; ks++) {
            uint32_t a[4];
            ldsm_x4(a, Qs_u + (aOff + ks * 8) * 4);
#pragma unroll
            for (int jj = 0; jj < 4; jj++) {
                uint32_t r4[4];
                ldsm_x4(r4, Ks_u + (kOff + jj * 16 * QP16 + ks * 8) * 4);
                mma_fp16(s[2 * jj], a, r4);
                mma_fp16(s[2 * jj + 1], a, r4 + 2);
            }
        }

        // ---- scale + mask; online softmax ----
        float tm0 = -1e30f, tm1 = -1e30f;
#pragma unroll
        for (int j = 0; j < 8; j++) {
            const bool d0 = (msk[j * 8 + 2 * t] == 0);
            const bool d1 = (msk[j * 8 + 2 * t + 1] == 0);
            s[j][0] = d0 ? -1e12f : s[j][0] * 0.125f;
            s[j][1] = d1 ? -1e12f : s[j][1] * 0.125f;
            s[j][2] = d0 ? -1e12f : s[j][2] * 0.125f;
            s[j][3] = d1 ? -1e12f : s[j][3] * 0.125f;
            tm0 = fmaxf(tm0, fmaxf(s[j][0], s[j][1]));
            tm1 = fmaxf(tm1, fmaxf(s[j][2], s[j][3]));
        }
        tm0 = fmaxf(tm0, __shfl_xor_sync(0xffffffffu, tm0, 1));
        tm0 = fmaxf(tm0, __shfl_xor_sync(0xffffffffu, tm0, 2));
        tm1 = fmaxf(tm1, __shfl_xor_sync(0xffffffffu, tm1, 1));
        tm1 = fmaxf(tm1, __shfl_xor_sync(0xffffffffu, tm1, 2));

        const float mn0 = fmaxf(m0, tm0), mn1 = fmaxf(m1, tm1);
        const float al0 = __expf(m0 - mn0), al1 = __expf(m1 - mn1);
        m0 = mn0; m1 = mn1;

        float ts0 = 0.f, ts1 = 0.f;
#pragma unroll
        for (int j = 0; j < 8; j++) {
            s[j][0] = __expf(s[j][0] - mn0);
            s[j][1] = __expf(s[j][1] - mn0);
            s[j][2] = __expf(s[j][2] - mn1);
            s[j][3] = __expf(s[j][3] - mn1);
            ts0 += s[j][0] + s[j][1];
            ts1 += s[j][2] + s[j][3];
        }
        ts0 += __shfl_xor_sync(0xffffffffu, ts0, 1);
        ts0 += __shfl_xor_sync(0xffffffffu, ts0, 2);
        ts1 += __shfl_xor_sync(0xffffffffu, ts1, 1);
        ts1 += __shfl_xor_sync(0xffffffffu, ts1, 2);
        l0 = l0 * al0 + ts0;
        l1 = l1 * al1 + ts1;

#pragma unroll
        for (int j = 0; j < 8; j++) {
            o[j][0] *= al0; o[j][1] *= al0;
            o[j][2] *= al1; o[j][3] *= al1;
        }

        // ---- stage P as row-major fp16 [q][key] ----
#pragma unroll
        for (int j = 0; j < 8; j++) {
            Ps[rowA * QP16 + j * 4 + t]       = pack_h2(s[j][0], s[j][1]);
            Ps[(rowA + 8) * QP16 + j * 4 + t] = pack_h2(s[j][2], s[j][3]);
        }
        __syncwarp();

        // ---- O += P V : 4 ks-steps over keys; V row-major via trans ----
#pragma unroll
        for (int ks = 0; ks < 4; ks++) {
            uint32_t a[4];
            ldsm_x4(a, Ps_u + (aOff + ks * 8) * 4);
#pragma unroll
            for (int jj = 0; jj < 4; jj++) {
                uint32_t r4[4];
                ldsm_x4t(r4, Vs_u + (vOff + ks * 16 * QP16 + jj * 8) * 4);
                mma_fp16(o[2 * jj], a, r4);
                mma_fp16(o[2 * jj + 1], a, r4 + 2);
            }
        }
    }

    // ---- epilogue: X16 = fp16(0.5 * O / l) ----
    const float sc0 = 0.5f / l0, sc1 = 0.5f / l1;
    __half2* Xr0 = (__half2*)X + ((size_t)b * 1024 + q0 + rowA) * 512 + h * 32;
    __half2* Xr1 = Xr0 + (size_t)8 * 512;
#pragma unroll
    for (int j = 0; j < 8; j++) {
        Xr0[j * 4 + t] = __floats2half2_rn(o[j][0] * sc0, o[j][1] * sc0);
        Xr1[j * 4 + t] = __floats2half2_rn(o[j][2] * sc1, o[j][3] * sc1);
    }
}

// ---------------------------------------------------------------------------
extern "C" void kernel_launch(void* const* d_in, const int* in_sizes, int n_in,
                              void* d_out, int out_size)
{
    const float* query = (const float*)d_in[0];
    const float* key   = (const float*)d_in[1];
    const float* value = (const float*)d_in[2];
    const float* adj   = (const float*)d_in[3];
    const int*   mask  = (const int*)d_in[5];
    const float* Wq = (const float*)d_in[6];
    const float* bq = (const float*)d_in[7];
    const float* Wk = (const float*)d_in[8];
    const float* bk = (const float*)d_in[9];
    const float* Wv = (const float*)d_in[10];
    const float* bv = (const float*)d_in[11];
    const float* Wo = (const float*)d_in[12];
    const float* bo = (const float*)d_in[13];
    float* out = (float*)d_out;

    __half *pQ, *pK, *pV, *pX, *pIn, *pW;
    float *pInv;
    cudaGetSymbolAddress((void**)&pQ, g_Q16);
    cudaGetSymbolAddress((void**)&pK, g_K16);
    cudaGetSymbolAddress((void**)&pV, g_V16);
    cudaGetSymbolAddress((void**)&pX, g_X16);
    cudaGetSymbolAddress((void**)&pIn, g_in16);
    cudaGetSymbolAddress((void**)&pW, g_W16);
    cudaGetSymbolAddress((void**)&pInv, g_inv);

    const size_t M8 = 8u * 1024u * 1024u;
    const size_t M1 = 1024u * 1024u;

    cudaFuncSetAttribute(gemm_fp16, cudaFuncAttributeMaxDynamicSharedMemorySize, GEMM_SMEM);
    cudaFuncSetAttribute(attn_fp16, cudaFuncAttributeMaxDynamicSharedMemorySize, ATT_SMEM);

    // conversions + rowsum (independent)
    cvt_in4<<<dim3(4096, 4), 256>>>(query, key, value, adj, pIn);
    cvt_w4<<<dim3(512, 4), 256>>>(Wq, Wk, Wv, Wo, pW);
    rowsum_inv<<<1024, 256>>>(adj, pInv);

    // fused QKV projection (fp16 out)
    {
        GemmArgs a{};
        a.A[0] = pIn; a.A[1] = pIn + M8; a.A[2] = pIn + 2 * M8;
        a.B[0] = pW; a.B[1] = pW + M1; a.B[2] = pW + 2 * M1;
        a.bias[0] = bq; a.bias[1] = bk; a.bias[2] = bv;
        a.C[0] = pQ; a.C[1] = pK; a.C[2] = pV;
        a.inv = pInv; a.Xin = pX;
        a.sA = a.sB = a.sC = 0;
        a.nsel = 3; a.cmode = 0;
        gemm_fp16<<<dim3(8, 64, 3), 128, GEMM_SMEM>>>(a);
    }

    // attention half -> X16 (V consumed row-major)
    attn_fp16<<<dim3(16, 16, 8), 128, ATT_SMEM>>>(pQ, pK, pV, mask, pX);

    // adjacency half: X16 = fp16(0.5*diag(inv)*(adj@V) + X16), batched
    {
        GemmArgs a{};
        a.A[0] = pIn + 3 * M8;   // adj fp16 row-major
        a.B[0] = pV;             // V fp16 row-major (trans fragments)
        a.bias[0] = bq;          // unused
        a.C[0] = pX;
        a.inv = pInv; a.Xin = pX;
        a.sA = M1; a.sB = M1; a.sC = M1;
        a.nsel = 1; a.cmode = 1;
        gemm_fp16<<<dim3(8, 8, 8), 128, GEMM_SMEM>>>(a);
    }

    // output projection (fp32 out + bias)
    {
        GemmArgs a{};
        a.A[0] = pX;
        a.B[0] = pW + 3 * M1;
        a.bias[0] = bo;
        a.C[0] = out;
        a.inv = pInv; a.Xin = pX;
        a.sA = a.sB = a.sC = 0;
        a.nsel = 1; a.cmode = 2;
        gemm_fp16<<<dim3(8, 64, 1), 128, GEMM_SMEM>>>(a);
    }
}